// round 1
// baseline (speedup 1.0000x reference)
#include <cuda_runtime.h>
#include <math.h>

#define BB    16
#define NN    4096
#define DIMK  512
#define NH    8
#define HD    64
#define INNER 512
#define MTOT  (BB * NN)   // 65536
#define BHH   (BB * NH)   // 128

// ---- scratch (static device globals; no allocations allowed) ----
__device__ float g_Q[(size_t)BHH * NN * HD];        // 134 MB
__device__ float g_K[(size_t)BHH * NN * HD];        // 134 MB
__device__ float g_V[(size_t)BHH * NN * HD];        // 134 MB
__device__ float g_attn[(size_t)MTOT * INNER];      // 134 MB
__device__ float g_kvp[8][BHH * HD * HD];           // 16.8 MB partials
__device__ float g_ksp[8][BHH * HD];                // 256 KB partials
__device__ float g_kv[BHH * HD * HD];
__device__ float g_ksum[BHH * HD];

// ============================================================
// Kernel 1: qkv = X @ W_qkv^T, fused activation, scatter to Q/K/V
//   X: [65536, 512], W: [1536, 512]  (both K-major -> NT gemm)
//   tile 128x128x16, 256 threads, 8x8 per thread
// ============================================================
__global__ __launch_bounds__(256, 2) void k_gemm_qkv(const float* __restrict__ X,
                                                     const float* __restrict__ W) {
    __shared__ float As[16][132];
    __shared__ float Bs[16][132];
    const int tid = threadIdx.x;
    const int m0 = blockIdx.x * 128;
    const int j0 = blockIdx.y * 128;
    const int lr = tid >> 2;         // 0..63
    const int lc = tid & 3;          // 0..3 (float4 col)
    const int tm = (tid >> 4) * 8;   // 0..120
    const int tn = (tid & 15) * 8;

    float acc[8][8];
#pragma unroll
    for (int i = 0; i < 8; i++)
#pragma unroll
        for (int j = 0; j < 8; j++) acc[i][j] = 0.f;

    for (int k0 = 0; k0 < DIMK; k0 += 16) {
#pragma unroll
        for (int i = 0; i < 2; i++) {
            int r = lr + i * 64;
            float4 a = *(const float4*)(X + (size_t)(m0 + r) * DIMK + k0 + lc * 4);
            As[lc * 4 + 0][r] = a.x; As[lc * 4 + 1][r] = a.y;
            As[lc * 4 + 2][r] = a.z; As[lc * 4 + 3][r] = a.w;
            float4 b = *(const float4*)(W + (size_t)(j0 + r) * DIMK + k0 + lc * 4);
            Bs[lc * 4 + 0][r] = b.x; Bs[lc * 4 + 1][r] = b.y;
            Bs[lc * 4 + 2][r] = b.z; Bs[lc * 4 + 3][r] = b.w;
        }
        __syncthreads();
#pragma unroll
        for (int kk = 0; kk < 16; kk++) {
            float a[8], b[8];
            *(float4*)&a[0] = *(const float4*)&As[kk][tm];
            *(float4*)&a[4] = *(const float4*)&As[kk][tm + 4];
            *(float4*)&b[0] = *(const float4*)&Bs[kk][tn];
            *(float4*)&b[4] = *(const float4*)&Bs[kk][tn + 4];
#pragma unroll
            for (int i = 0; i < 8; i++)
#pragma unroll
                for (int j = 0; j < 8; j++)
                    acc[i][j] = fmaf(a[i], b[j], acc[i][j]);
        }
        __syncthreads();
    }

    // epilogue: activation on q/k, scatter to head-major layout
    const int j = j0 + tn;           // 8 consecutive columns, within one of q/k/v
    const int which = j >> 9;        // 0=q, 1=k, 2=v
    const int h = (j >> 6) & 7;
    const int dd = j & 63;           // multiple of 8
    float* dst = (which == 0) ? g_Q : ((which == 1) ? g_K : g_V);
#pragma unroll
    for (int i = 0; i < 8; i++) {
        int m = m0 + tm + i;
        int b_ = m >> 12, n_ = m & 4095;
        size_t off = ((size_t)(b_ * NH + h) * NN + n_) * HD + dd;
        float v0[8];
#pragma unroll
        for (int jj = 0; jj < 8; jj++) {
            float v = acc[i][jj];
            if (which < 2) v = (v > 0.f) ? (v + 1.f) : expf(v);
            v0[jj] = v;
        }
        *(float4*)(dst + off)     = *(float4*)&v0[0];
        *(float4*)(dst + off + 4) = *(float4*)&v0[4];
    }
}

// ============================================================
// Kernel 2: per-(b,h) partial kv = K^T V over 512-row n chunks,
// plus partial k_sum. Deterministic partials (no atomics).
// grid: (128, 8), 256 threads, 4x4 per thread over 64x64 output
// ============================================================
__global__ __launch_bounds__(256) void k_kv() {
    const int bh = blockIdx.x;
    const int chunk = blockIdx.y;    // 0..7
    const size_t base = ((size_t)bh * NN + (size_t)chunk * (NN / 8)) * HD;
    const float* Kp = g_K + base;
    const float* Vp = g_V + base;
    __shared__ float Ks[32][64];
    __shared__ float Vs[32][64];
    const int tid = threadIdx.x;
    const int td = (tid >> 4) * 4;   // 0..60
    const int te = (tid & 15) * 4;   // 0..60

    float acc[4][4];
#pragma unroll
    for (int i = 0; i < 4; i++)
#pragma unroll
        for (int j = 0; j < 4; j++) acc[i][j] = 0.f;
    float ks[4] = {0.f, 0.f, 0.f, 0.f};
    const bool do_ks = (te == 0);

    for (int nt = 0; nt < NN / 8; nt += 32) {
#pragma unroll
        for (int i = 0; i < 2; i++) {
            int idx = tid + i * 256;          // float4 index 0..511
            int r = idx >> 4, c = (idx & 15) * 4;
            *(float4*)&Ks[r][c] = *(const float4*)(Kp + (size_t)(nt + r) * HD + c);
            *(float4*)&Vs[r][c] = *(const float4*)(Vp + (size_t)(nt + r) * HD + c);
        }
        __syncthreads();
#pragma unroll 8
        for (int n = 0; n < 32; n++) {
            float4 kk = *(const float4*)&Ks[n][td];
            float4 vv = *(const float4*)&Vs[n][te];
            float ka[4] = {kk.x, kk.y, kk.z, kk.w};
            float va[4] = {vv.x, vv.y, vv.z, vv.w};
#pragma unroll
            for (int i = 0; i < 4; i++)
#pragma unroll
                for (int j = 0; j < 4; j++)
                    acc[i][j] = fmaf(ka[i], va[j], acc[i][j]);
            if (do_ks) {
                ks[0] += ka[0]; ks[1] += ka[1]; ks[2] += ka[2]; ks[3] += ka[3];
            }
        }
        __syncthreads();
    }

    float* kvp = g_kvp[chunk] + (size_t)bh * HD * HD;
#pragma unroll
    for (int i = 0; i < 4; i++) {
        float4 v = make_float4(acc[i][0], acc[i][1], acc[i][2], acc[i][3]);
        *(float4*)(kvp + (td + i) * HD + te) = v;
    }
    if (do_ks) {
        float4 v = make_float4(ks[0], ks[1], ks[2], ks[3]);
        *(float4*)(g_ksp[chunk] + bh * HD + td) = v;
    }
}

// ============================================================
// Kernel 3: reduce 8 partials -> g_kv, g_ksum
// ============================================================
__global__ void k_reduce() {
    int i = blockIdx.x * 256 + threadIdx.x;   // 0..524287
    float s = 0.f;
#pragma unroll
    for (int p = 0; p < 8; p++) s += g_kvp[p][i];
    g_kv[i] = s;
    if (i < BHH * HD) {
        float t = 0.f;
#pragma unroll
        for (int p = 0; p < 8; p++) t += g_ksp[p][i];
        g_ksum[i] = t;
    }
}

// ============================================================
// Kernel 4: attn[m, h*64+e] = z * sum_d Q[bh,n,d] * kv[bh,d,e]
//   z = 1/max(q . ksum, eps). grid (128, 64), 256 threads.
// ============================================================
__global__ __launch_bounds__(256) void k_attn() {
    const int bh = blockIdx.x;
    const int nt = blockIdx.y;       // 64-row n tile
    __shared__ float KVs[64][68];
    __shared__ float Qs[64][68];
    __shared__ float KS[64];
    const int tid = threadIdx.x;
    const float* kvp = g_kv + (size_t)bh * HD * HD;
    const float* Qp = g_Q + ((size_t)bh * NN + nt * 64) * HD;
#pragma unroll
    for (int i = 0; i < 4; i++) {
        int idx = tid + i * 256;     // float4 idx 0..1023
        int r = idx >> 4, c = (idx & 15) * 4;
        *(float4*)&KVs[r][c] = *(const float4*)(kvp + r * HD + c);
        *(float4*)&Qs[r][c]  = *(const float4*)(Qp + (size_t)r * HD + c);
    }
    if (tid < 64) KS[tid] = g_ksum[bh * HD + tid];
    __syncthreads();

    const int tn = tid >> 2;         // n row within tile
    const int qe = (tid & 3) * 16;   // e range start
    float acc[16];
#pragma unroll
    for (int j = 0; j < 16; j++) acc[j] = 0.f;
    float dot = 0.f;
#pragma unroll 16
    for (int d = 0; d < 64; d++) {
        float qv = Qs[tn][d];
        dot = fmaf(qv, KS[d], dot);
#pragma unroll
        for (int j = 0; j < 16; j++)
            acc[j] = fmaf(qv, KVs[d][qe + j], acc[j]);
    }
    float z = 1.f / fmaxf(dot, 1e-4f);
    const int b_ = bh >> 3, h = bh & 7;
    const int n = nt * 64 + tn;
    float* op = g_attn + ((size_t)(b_ * NN + n)) * INNER + h * HD + qe;
#pragma unroll
    for (int j = 0; j < 16; j += 4) {
        float4 v = make_float4(acc[j] * z, acc[j + 1] * z, acc[j + 2] * z, acc[j + 3] * z);
        *(float4*)(op + j) = v;
    }
}

// ============================================================
// Kernel 5: out = attn @ W_out^T + b_out
//   attn: [65536, 512], W_out: [512, 512]
// ============================================================
__global__ __launch_bounds__(256, 2) void k_gemm_out(const float* __restrict__ Wo,
                                                     const float* __restrict__ bias,
                                                     float* __restrict__ out) {
    __shared__ float As[16][132];
    __shared__ float Bs[16][132];
    const int tid = threadIdx.x;
    const int m0 = blockIdx.x * 128;
    const int j0 = blockIdx.y * 128;
    const int lr = tid >> 2;
    const int lc = tid & 3;
    const int tm = (tid >> 4) * 8;
    const int tn = (tid & 15) * 8;

    float acc[8][8];
#pragma unroll
    for (int i = 0; i < 8; i++)
#pragma unroll
        for (int j = 0; j < 8; j++) acc[i][j] = 0.f;

    const float* A = g_attn;
    for (int k0 = 0; k0 < INNER; k0 += 16) {
#pragma unroll
        for (int i = 0; i < 2; i++) {
            int r = lr + i * 64;
            float4 a = *(const float4*)(A + (size_t)(m0 + r) * INNER + k0 + lc * 4);
            As[lc * 4 + 0][r] = a.x; As[lc * 4 + 1][r] = a.y;
            As[lc * 4 + 2][r] = a.z; As[lc * 4 + 3][r] = a.w;
            float4 b = *(const float4*)(Wo + (size_t)(j0 + r) * INNER + k0 + lc * 4);
            Bs[lc * 4 + 0][r] = b.x; Bs[lc * 4 + 1][r] = b.y;
            Bs[lc * 4 + 2][r] = b.z; Bs[lc * 4 + 3][r] = b.w;
        }
        __syncthreads();
#pragma unroll
        for (int kk = 0; kk < 16; kk++) {
            float a[8], b[8];
            *(float4*)&a[0] = *(const float4*)&As[kk][tm];
            *(float4*)&a[4] = *(const float4*)&As[kk][tm + 4];
            *(float4*)&b[0] = *(const float4*)&Bs[kk][tn];
            *(float4*)&b[4] = *(const float4*)&Bs[kk][tn + 4];
#pragma unroll
            for (int i = 0; i < 8; i++)
#pragma unroll
                for (int j = 0; j < 8; j++)
                    acc[i][j] = fmaf(a[i], b[j], acc[i][j]);
        }
        __syncthreads();
    }

    const int j = j0 + tn;
    float bv[8];
    *(float4*)&bv[0] = *(const float4*)(bias + j);
    *(float4*)&bv[4] = *(const float4*)(bias + j + 4);
#pragma unroll
    for (int i = 0; i < 8; i++) {
        int m = m0 + tm + i;
        float v0[8];
#pragma unroll
        for (int jj = 0; jj < 8; jj++) v0[jj] = acc[i][jj] + bv[jj];
        *(float4*)(out + (size_t)m * INNER + j)     = *(float4*)&v0[0];
        *(float4*)(out + (size_t)m * INNER + j + 4) = *(float4*)&v0[4];
    }
}

// ============================================================
extern "C" void kernel_launch(void* const* d_in, const int* in_sizes, int n_in,
                              void* d_out, int out_size) {
    const float* x     = (const float*)d_in[0];
    const float* W_qkv = (const float*)d_in[1];
    const float* W_out = (const float*)d_in[2];
    const float* b_out = (const float*)d_in[3];
    float* out = (float*)d_out;

    dim3 g1(MTOT / 128, 1536 / 128);
    k_gemm_qkv<<<g1, 256>>>(x, W_qkv);

    dim3 g2(BHH, 8);
    k_kv<<<g2, 256>>>();

    k_reduce<<<(BHH * HD * HD) / 256, 256>>>();

    dim3 g3(BHH, NN / 64);
    k_attn<<<g3, 256>>>();

    dim3 g4(MTOT / 128, INNER / 128);
    k_gemm_out<<<g4, 256>>>(W_out, b_out, out);
}

// round 3
// speedup vs baseline: 2.0943x; 2.0943x over previous
#include <cuda_runtime.h>
#include <cuda_bf16.h>
#include <math.h>
#include <stdint.h>

#define BB    16
#define NN    4096
#define DIMK  512
#define NH    8
#define HD    64
#define INNER 512
#define MTOT  (BB * NN)   // 65536
#define BHH   (BB * NH)   // 128

// ---------------- scratch (static device globals) ----------------
__device__ __align__(256) float g_Q[(size_t)BHH * NN * HD];
__device__ __align__(256) float g_K[(size_t)BHH * NN * HD];
__device__ __align__(256) float g_V[(size_t)BHH * NN * HD];
__device__ __align__(256) __nv_bfloat16 g_Xhi[(size_t)MTOT * DIMK];
__device__ __align__(256) __nv_bfloat16 g_Xlo[(size_t)MTOT * DIMK];
__device__ __align__(256) __nv_bfloat16 g_AThi[(size_t)MTOT * INNER];
__device__ __align__(256) __nv_bfloat16 g_ATlo[(size_t)MTOT * INNER];
__device__ __align__(256) __nv_bfloat16 g_W1hi[1536 * DIMK];
__device__ __align__(256) __nv_bfloat16 g_W1lo[1536 * DIMK];
__device__ __align__(256) __nv_bfloat16 g_W2hi[INNER * INNER];
__device__ __align__(256) __nv_bfloat16 g_W2lo[INNER * INNER];
__device__ float g_kvp[8][BHH * HD * HD];
__device__ float g_ksp[8][BHH * HD];
__device__ float g_kv[BHH * HD * HD];
__device__ float g_ksum[BHH * HD];

// ---------------- helpers ----------------
__device__ __forceinline__ uint32_t smem_u32(const void* p) {
    uint32_t a;
    asm("{ .reg .u64 t; cvta.to.shared.u64 t, %1; cvt.u32.u64 %0, t; }" : "=r"(a) : "l"(p));
    return a;
}
__device__ __forceinline__ void cp16(uint32_t dst, const void* src) {
    asm volatile("cp.async.cg.shared.global [%0], [%1], 16;" ::
                 "r"(dst), "l"(__cvta_generic_to_global(src)) : "memory");
}
#define CP_COMMIT() asm volatile("cp.async.commit_group;" ::: "memory")
#define CP_WAIT(n)  asm volatile("cp.async.wait_group %0;" :: "n"(n) : "memory")

#define LDSM4(R, A)                                                          \
    asm volatile("ldmatrix.sync.aligned.m8n8.x4.shared.b16 {%0,%1,%2,%3}, [%4];" \
                 : "=r"((R)[0]), "=r"((R)[1]), "=r"((R)[2]), "=r"((R)[3])    \
                 : "r"(A))

__device__ __forceinline__ void mma16816(float* c, const uint32_t* a, const uint32_t* b) {
    asm volatile(
        "mma.sync.aligned.m16n8k16.row.col.f32.bf16.bf16.f32 "
        "{%0,%1,%2,%3}, {%4,%5,%6,%7}, {%8,%9}, {%0,%1,%2,%3};"
        : "+f"(c[0]), "+f"(c[1]), "+f"(c[2]), "+f"(c[3])
        : "r"(a[0]), "r"(a[1]), "r"(a[2]), "r"(a[3]), "r"(b[0]), "r"(b[1]));
}

// ---------------- convert fp32 -> bf16 hi/lo ----------------
__global__ void k_convert(const float4* __restrict__ src, int which, int n4) {
    int i = blockIdx.x * 256 + threadIdx.x;
    if (i >= n4) return;
    uint2* hi;
    uint2* lo;
    if (which == 0)      { hi = (uint2*)g_Xhi;  lo = (uint2*)g_Xlo;  }
    else if (which == 1) { hi = (uint2*)g_W1hi; lo = (uint2*)g_W1lo; }
    else                 { hi = (uint2*)g_W2hi; lo = (uint2*)g_W2lo; }
    float4 v = src[i];
    __nv_bfloat16 h0 = __float2bfloat16(v.x), h1 = __float2bfloat16(v.y);
    __nv_bfloat16 h2 = __float2bfloat16(v.z), h3 = __float2bfloat16(v.w);
    __nv_bfloat16 l0 = __float2bfloat16(v.x - __bfloat162float(h0));
    __nv_bfloat16 l1 = __float2bfloat16(v.y - __bfloat162float(h1));
    __nv_bfloat16 l2 = __float2bfloat16(v.z - __bfloat162float(h2));
    __nv_bfloat16 l3 = __float2bfloat16(v.w - __bfloat162float(h3));
    uint2 H, L;
    H.x = (uint32_t)__bfloat16_as_ushort(h0) | ((uint32_t)__bfloat16_as_ushort(h1) << 16);
    H.y = (uint32_t)__bfloat16_as_ushort(h2) | ((uint32_t)__bfloat16_as_ushort(h3) << 16);
    L.x = (uint32_t)__bfloat16_as_ushort(l0) | ((uint32_t)__bfloat16_as_ushort(l1) << 16);
    L.y = (uint32_t)__bfloat16_as_ushort(l2) | ((uint32_t)__bfloat16_as_ushort(l3) << 16);
    hi[i] = H;
    lo[i] = L;
}

// ---------------- split-bf16 GEMM on mma.sync ----------------
// C[m][n] = sum_k A[m][k]*B[n][k].  K=512, BLK 128x128x32, 3-stage cp.async.
// SMEM row stride 80B (32 bf16 + 8 pad) -> conflict-free ldmatrix.
#define TILE_SZ 10240           // 128 rows * 80B
#define STAGE_SZ (4 * TILE_SZ)  // Ahi, Alo, Bhi, Blo
#define SMEM_T (3 * STAGE_SZ)   // 122880

template <int GEMM_ID>
__global__ __launch_bounds__(256) void k_gemm_mma(const float* __restrict__ bias,
                                                  float* __restrict__ outp) {
    extern __shared__ char smem[];
    const uint32_t sb = smem_u32(smem);
    const int tid = threadIdx.x;
    const int lane = tid & 31;
    const int wid = tid >> 5;
    const int warp_m = wid >> 2;  // 0..1
    const int warp_n = wid & 3;   // 0..3
    const int m0 = blockIdx.x * 128;
    const int n0 = blockIdx.y * 128;

    const __nv_bfloat16* Ahi = (GEMM_ID == 1) ? g_Xhi : g_AThi;
    const __nv_bfloat16* Alo = (GEMM_ID == 1) ? g_Xlo : g_ATlo;
    const __nv_bfloat16* Bhi = (GEMM_ID == 1) ? g_W1hi : g_W2hi;
    const __nv_bfloat16* Blo = (GEMM_ID == 1) ? g_W1lo : g_W2lo;

    float acc[4][4][4];
#pragma unroll
    for (int i = 0; i < 4; i++)
#pragma unroll
        for (int j = 0; j < 4; j++)
#pragma unroll
            for (int k = 0; k < 4; k++) acc[i][j][k] = 0.f;

    auto load_stage = [&](int s) {
        const int k0 = s * 32;
        const uint32_t st = sb + (s % 3) * STAGE_SZ;
#pragma unroll
        for (int i = 0; i < 2; i++) {
            int idx = tid + i * 256;
            int r = idx >> 2, c = idx & 3;
            uint32_t so = (uint32_t)r * 80 + c * 16;
            size_t ga = (size_t)(m0 + r) * DIMK + k0 + c * 8;
            size_t gb = (size_t)(n0 + r) * DIMK + k0 + c * 8;
            cp16(st + so,                Ahi + ga);
            cp16(st + TILE_SZ + so,      Alo + ga);
            cp16(st + 2 * TILE_SZ + so,  Bhi + gb);
            cp16(st + 3 * TILE_SZ + so,  Blo + gb);
        }
        CP_COMMIT();
    };

    load_stage(0);
    load_stage(1);

#pragma unroll 1
    for (int s = 0; s < 16; s++) {
        if (s < 14) {
            load_stage(s + 2);
            CP_WAIT(2);
        } else if (s == 14) {
            CP_WAIT(1);
        } else {
            CP_WAIT(0);
        }
        __syncthreads();
        const uint32_t st = sb + (s % 3) * STAGE_SZ;
        const uint32_t aH = st, aL = st + TILE_SZ;
        const uint32_t bH = st + 2 * TILE_SZ, bL = st + 3 * TILE_SZ;

#pragma unroll
        for (int kk = 0; kk < 2; kk++) {
            uint32_t ah[4][4], al[4][4];
            {
                const int row = warp_m * 64 + (lane & 15);
                const int kc = kk * 16 + (lane >> 4) * 8;
#pragma unroll
                for (int mt = 0; mt < 4; mt++) {
                    uint32_t off = (uint32_t)(row + mt * 16) * 80 + kc * 2;
                    LDSM4(ah[mt], aH + off);
                    LDSM4(al[mt], aL + off);
                }
            }
            const int grp = lane >> 3;
            const int brow = warp_n * 32 + ((grp & 2) << 2) + (lane & 7);
            const int bk = kk * 16 + (grp & 1) * 8;
#pragma unroll
            for (int np = 0; np < 2; np++) {
                uint32_t bh4[4], bl4[4];
                uint32_t off = (uint32_t)(brow + np * 16) * 80 + bk * 2;
                LDSM4(bh4, bH + off);
                LDSM4(bl4, bL + off);
#pragma unroll
                for (int half = 0; half < 2; half++) {
                    const int nt = np * 2 + half;
                    uint32_t bhf[2] = {bh4[half * 2], bh4[half * 2 + 1]};
                    uint32_t blf[2] = {bl4[half * 2], bl4[half * 2 + 1]};
#pragma unroll
                    for (int mt = 0; mt < 4; mt++) {
                        mma16816(acc[mt][nt], ah[mt], bhf);
                        mma16816(acc[mt][nt], al[mt], bhf);
                        mma16816(acc[mt][nt], ah[mt], blf);
                    }
                }
            }
        }
        __syncthreads();
    }

    // ---------------- epilogue ----------------
    const int r0 = lane >> 2;
    const int c0 = (lane & 3) * 2;
#pragma unroll
    for (int mt = 0; mt < 4; mt++) {
#pragma unroll
        for (int nt = 0; nt < 4; nt++) {
            const int col = n0 + warp_n * 32 + nt * 8 + c0;
#pragma unroll
            for (int ri = 0; ri < 2; ri++) {
                const int m = m0 + warp_m * 64 + mt * 16 + r0 + ri * 8;
                float v0 = acc[mt][nt][ri * 2];
                float v1 = acc[mt][nt][ri * 2 + 1];
                if (GEMM_ID == 1) {
                    const int which = col >> 9;
                    const int h = (col >> 6) & 7;
                    const int dd = col & 63;
                    float* dst = (which == 0) ? g_Q : (which == 1) ? g_K : g_V;
                    if (which < 2) {
                        v0 = (v0 > 0.f) ? v0 + 1.f : expf(v0);
                        v1 = (v1 > 0.f) ? v1 + 1.f : expf(v1);
                    }
                    const int b_ = m >> 12, n_ = m & 4095;
                    *(float2*)(dst + ((size_t)(b_ * NH + h) * NN + n_) * HD + dd) =
                        make_float2(v0, v1);
                } else {
                    *(float2*)(outp + (size_t)m * INNER + col) =
                        make_float2(v0 + __ldg(bias + col), v1 + __ldg(bias + col + 1));
                }
            }
        }
    }
}

// ---------------- kv partials ----------------
__global__ __launch_bounds__(256) void k_kv() {
    const int bh = blockIdx.x;
    const int chunk = blockIdx.y;
    const size_t base = ((size_t)bh * NN + (size_t)chunk * (NN / 8)) * HD;
    const float* Kp = g_K + base;
    const float* Vp = g_V + base;
    __shared__ float Ks[32][64];
    __shared__ float Vs[32][64];
    const int tid = threadIdx.x;
    const int td = (tid >> 4) * 4;
    const int te = (tid & 15) * 4;

    float acc[4][4];
#pragma unroll
    for (int i = 0; i < 4; i++)
#pragma unroll
        for (int j = 0; j < 4; j++) acc[i][j] = 0.f;
    float ks[4] = {0.f, 0.f, 0.f, 0.f};
    const bool do_ks = (te == 0);

    for (int nt = 0; nt < NN / 8; nt += 32) {
#pragma unroll
        for (int i = 0; i < 2; i++) {
            int idx = tid + i * 256;
            int r = idx >> 4, c = (idx & 15) * 4;
            *(float4*)&Ks[r][c] = *(const float4*)(Kp + (size_t)(nt + r) * HD + c);
            *(float4*)&Vs[r][c] = *(const float4*)(Vp + (size_t)(nt + r) * HD + c);
        }
        __syncthreads();
#pragma unroll 8
        for (int n = 0; n < 32; n++) {
            float4 kk = *(const float4*)&Ks[n][td];
            float4 vv = *(const float4*)&Vs[n][te];
            float ka[4] = {kk.x, kk.y, kk.z, kk.w};
            float va[4] = {vv.x, vv.y, vv.z, vv.w};
#pragma unroll
            for (int i = 0; i < 4; i++)
#pragma unroll
                for (int j = 0; j < 4; j++)
                    acc[i][j] = fmaf(ka[i], va[j], acc[i][j]);
            if (do_ks) {
                ks[0] += ka[0]; ks[1] += ka[1]; ks[2] += ka[2]; ks[3] += ka[3];
            }
        }
        __syncthreads();
    }

    float* kvp = g_kvp[chunk] + (size_t)bh * HD * HD;
#pragma unroll
    for (int i = 0; i < 4; i++)
        *(float4*)(kvp + (td + i) * HD + te) =
            make_float4(acc[i][0], acc[i][1], acc[i][2], acc[i][3]);
    if (do_ks)
        *(float4*)(g_ksp[chunk] + bh * HD + td) = make_float4(ks[0], ks[1], ks[2], ks[3]);
}

__global__ void k_reduce() {
    int i = blockIdx.x * 256 + threadIdx.x;
    float s = 0.f;
#pragma unroll
    for (int p = 0; p < 8; p++) s += g_kvp[p][i];
    g_kv[i] = s;
    if (i < BHH * HD) {
        float t = 0.f;
#pragma unroll
        for (int p = 0; p < 8; p++) t += g_ksp[p][i];
        g_ksum[i] = t;
    }
}

// ---------------- attn: 4x4 blocking, bf16 hi/lo output ----------------
__global__ __launch_bounds__(256) void k_attn() {
    const int bh = blockIdx.x;
    const int nt = blockIdx.y;
    __shared__ float KVs[64][68];
    __shared__ float Qs[64][68];
    __shared__ float KS[64];
    const int tid = threadIdx.x;
    const float* kvp = g_kv + (size_t)bh * HD * HD;
    const float* Qp = g_Q + ((size_t)bh * NN + nt * 64) * HD;
#pragma unroll
    for (int i = 0; i < 4; i++) {
        int idx = tid + i * 256;
        int r = idx >> 4, c = (idx & 15) * 4;
        *(float4*)&KVs[r][c] = *(const float4*)(kvp + r * HD + c);
        *(float4*)&Qs[r][c] = *(const float4*)(Qp + (size_t)r * HD + c);
    }
    if (tid < 64) KS[tid] = g_ksum[bh * HD + tid];
    __syncthreads();

    const int te = (tid & 15) * 4;
    const int tn = (tid >> 4) * 4;
    float acc[4][4];
#pragma unroll
    for (int i = 0; i < 4; i++)
#pragma unroll
        for (int j = 0; j < 4; j++) acc[i][j] = 0.f;
    float dot[4] = {0.f, 0.f, 0.f, 0.f};

#pragma unroll 8
    for (int d = 0; d < 64; d++) {
        float4 kv4 = *(const float4*)&KVs[d][te];
        float ksd = KS[d];
        float q[4];
#pragma unroll
        for (int i = 0; i < 4; i++) q[i] = Qs[tn + i][d];
#pragma unroll
        for (int i = 0; i < 4; i++) {
            dot[i] = fmaf(q[i], ksd, dot[i]);
            acc[i][0] = fmaf(q[i], kv4.x, acc[i][0]);
            acc[i][1] = fmaf(q[i], kv4.y, acc[i][1]);
            acc[i][2] = fmaf(q[i], kv4.z, acc[i][2]);
            acc[i][3] = fmaf(q[i], kv4.w, acc[i][3]);
        }
    }
    const int b_ = bh >> 3, h = bh & 7;
#pragma unroll
    for (int i = 0; i < 4; i++) {
        float z = 1.f / fmaxf(dot[i], 1e-4f);
        int n = nt * 64 + tn + i;
        size_t off = ((size_t)(b_ * NN + n)) * INNER + h * HD + te;
        float v[4];
#pragma unroll
        for (int j = 0; j < 4; j++) v[j] = acc[i][j] * z;
        __nv_bfloat16 hh[4], ll[4];
#pragma unroll
        for (int j = 0; j < 4; j++) {
            hh[j] = __float2bfloat16(v[j]);
            ll[j] = __float2bfloat16(v[j] - __bfloat162float(hh[j]));
        }
        uint2 H, L;
        H.x = (uint32_t)__bfloat16_as_ushort(hh[0]) | ((uint32_t)__bfloat16_as_ushort(hh[1]) << 16);
        H.y = (uint32_t)__bfloat16_as_ushort(hh[2]) | ((uint32_t)__bfloat16_as_ushort(hh[3]) << 16);
        L.x = (uint32_t)__bfloat16_as_ushort(ll[0]) | ((uint32_t)__bfloat16_as_ushort(ll[1]) << 16);
        L.y = (uint32_t)__bfloat16_as_ushort(ll[2]) | ((uint32_t)__bfloat16_as_ushort(ll[3]) << 16);
        *(uint2*)(g_AThi + off) = H;
        *(uint2*)(g_ATlo + off) = L;
    }
}

// ---------------- launch ----------------
extern "C" void kernel_launch(void* const* d_in, const int* in_sizes, int n_in,
                              void* d_out, int out_size) {
    const float* x = (const float*)d_in[0];
    const float* W_qkv = (const float*)d_in[1];
    const float* W_out = (const float*)d_in[2];
    const float* b_out = (const float*)d_in[3];
    float* out = (float*)d_out;

    static int attr_done = 0;
    if (!attr_done) {
        cudaFuncSetAttribute((const void*)k_gemm_mma<1>,
                             cudaFuncAttributeMaxDynamicSharedMemorySize, SMEM_T);
        cudaFuncSetAttribute((const void*)k_gemm_mma<2>,
                             cudaFuncAttributeMaxDynamicSharedMemorySize, SMEM_T);
        attr_done = 1;
    }

    k_convert<<<(MTOT * DIMK / 4) / 256, 256>>>((const float4*)x, 0, MTOT * DIMK / 4);
    k_convert<<<(1536 * DIMK / 4) / 256, 256>>>((const float4*)W_qkv, 1, 1536 * DIMK / 4);
    k_convert<<<(INNER * INNER / 4) / 256, 256>>>((const float4*)W_out, 2, INNER * INNER / 4);

    dim3 g1(MTOT / 128, 1536 / 128);
    k_gemm_mma<1><<<g1, 256, SMEM_T>>>(nullptr, nullptr);

    dim3 g2(BHH, 8);
    k_kv<<<g2, 256>>>();
    k_reduce<<<(BHH * HD * HD) / 256, 256>>>();

    dim3 g3(BHH, NN / 64);
    k_attn<<<g3, 256>>>();

    dim3 g4(MTOT / 128, INNER / 128);
    k_gemm_mma<2><<<g4, 256, SMEM_T>>>(b_out, out);
}

// round 4
// speedup vs baseline: 2.5613x; 1.2230x over previous
#include <cuda_runtime.h>
#include <cuda_bf16.h>
#include <math.h>
#include <stdint.h>

#define BB    16
#define NN    4096
#define DIMK  512
#define NH    8
#define HD    64
#define INNER 512
#define MTOT  (BB * NN)   // 65536
#define BHH   (BB * NH)   // 128

// ---------------- scratch (static device globals) ----------------
__device__ __align__(256) float g_Q[(size_t)BHH * NN * HD];
__device__ __align__(256) float g_K[(size_t)BHH * NN * HD];
__device__ __align__(256) float g_V[(size_t)BHH * NN * HD];
__device__ __align__(256) __nv_bfloat16 g_Xhi[(size_t)MTOT * DIMK];
__device__ __align__(256) __nv_bfloat16 g_Xlo[(size_t)MTOT * DIMK];
__device__ __align__(256) __nv_bfloat16 g_AThi[(size_t)MTOT * INNER];
__device__ __align__(256) __nv_bfloat16 g_ATlo[(size_t)MTOT * INNER];
__device__ __align__(256) __nv_bfloat16 g_W1hi[1536 * DIMK];
__device__ __align__(256) __nv_bfloat16 g_W1lo[1536 * DIMK];
__device__ __align__(256) __nv_bfloat16 g_W2hi[INNER * INNER];
__device__ __align__(256) __nv_bfloat16 g_W2lo[INNER * INNER];
__device__ float g_kvp[8][BHH * HD * HD];
__device__ float g_ksp[8][BHH * HD];
__device__ float g_kv[BHH * HD * HD];
__device__ float g_ksum[BHH * HD];

// ---------------- helpers ----------------
__device__ __forceinline__ uint32_t smem_u32(const void* p) {
    uint32_t a;
    asm("{ .reg .u64 t; cvta.to.shared.u64 t, %1; cvt.u32.u64 %0, t; }" : "=r"(a) : "l"(p));
    return a;
}
__device__ __forceinline__ void cp16(uint32_t dst, const void* src) {
    asm volatile("cp.async.cg.shared.global [%0], [%1], 16;" ::
                 "r"(dst), "l"(__cvta_generic_to_global(src)) : "memory");
}
#define CP_COMMIT() asm volatile("cp.async.commit_group;" ::: "memory")
#define CP_WAIT(n)  asm volatile("cp.async.wait_group %0;" :: "n"(n) : "memory")

#define LDSM4(R, A)                                                          \
    asm volatile("ldmatrix.sync.aligned.m8n8.x4.shared.b16 {%0,%1,%2,%3}, [%4];" \
                 : "=r"((R)[0]), "=r"((R)[1]), "=r"((R)[2]), "=r"((R)[3])    \
                 : "r"(A))

__device__ __forceinline__ void mma16816(float* c, const uint32_t* a, const uint32_t* b) {
    asm volatile(
        "mma.sync.aligned.m16n8k16.row.col.f32.bf16.bf16.f32 "
        "{%0,%1,%2,%3}, {%4,%5,%6,%7}, {%8,%9}, {%0,%1,%2,%3};"
        : "+f"(c[0]), "+f"(c[1]), "+f"(c[2]), "+f"(c[3])
        : "r"(a[0]), "r"(a[1]), "r"(a[2]), "r"(a[3]), "r"(b[0]), "r"(b[1]));
}

// ---------------- convert fp32 -> bf16 hi/lo ----------------
__global__ void k_convert(const float4* __restrict__ src, int which, int n4) {
    int i = blockIdx.x * 256 + threadIdx.x;
    if (i >= n4) return;
    uint2* hi;
    uint2* lo;
    if (which == 0)      { hi = (uint2*)g_Xhi;  lo = (uint2*)g_Xlo;  }
    else if (which == 1) { hi = (uint2*)g_W1hi; lo = (uint2*)g_W1lo; }
    else                 { hi = (uint2*)g_W2hi; lo = (uint2*)g_W2lo; }
    float4 v = src[i];
    __nv_bfloat16 h0 = __float2bfloat16(v.x), h1 = __float2bfloat16(v.y);
    __nv_bfloat16 h2 = __float2bfloat16(v.z), h3 = __float2bfloat16(v.w);
    __nv_bfloat16 l0 = __float2bfloat16(v.x - __bfloat162float(h0));
    __nv_bfloat16 l1 = __float2bfloat16(v.y - __bfloat162float(h1));
    __nv_bfloat16 l2 = __float2bfloat16(v.z - __bfloat162float(h2));
    __nv_bfloat16 l3 = __float2bfloat16(v.w - __bfloat162float(h3));
    uint2 H, L;
    H.x = (uint32_t)__bfloat16_as_ushort(h0) | ((uint32_t)__bfloat16_as_ushort(h1) << 16);
    H.y = (uint32_t)__bfloat16_as_ushort(h2) | ((uint32_t)__bfloat16_as_ushort(h3) << 16);
    L.x = (uint32_t)__bfloat16_as_ushort(l0) | ((uint32_t)__bfloat16_as_ushort(l1) << 16);
    L.y = (uint32_t)__bfloat16_as_ushort(l2) | ((uint32_t)__bfloat16_as_ushort(l3) << 16);
    hi[i] = H;
    lo[i] = L;
}

// ---------------- split-bf16 GEMM on mma.sync ----------------
// C[m][n] = sum_k A[m][k]*B[n][k].  K=512, BLK 128x128x32, 2-stage cp.async,
// 2 CTAs/SM. grid.x = n-blocks (so B is L2-resident, A read once).
#define TILE_SZ 10240           // 128 rows * 80B
#define STAGE_SZ (4 * TILE_SZ)  // Ahi, Alo, Bhi, Blo
#define SMEM_T (2 * STAGE_SZ)   // 81920

template <int GEMM_ID>
__global__ __launch_bounds__(256, 2) void k_gemm_mma(const float* __restrict__ bias,
                                                     float* __restrict__ outp) {
    extern __shared__ char smem[];
    const uint32_t sb = smem_u32(smem);
    const int tid = threadIdx.x;
    const int lane = tid & 31;
    const int wid = tid >> 5;
    const int warp_m = wid >> 2;  // 0..1
    const int warp_n = wid & 3;   // 0..3
    const int m0 = blockIdx.y * 128;
    const int n0 = blockIdx.x * 128;

    const __nv_bfloat16* Ahi = (GEMM_ID == 1) ? g_Xhi : g_AThi;
    const __nv_bfloat16* Alo = (GEMM_ID == 1) ? g_Xlo : g_ATlo;
    const __nv_bfloat16* Bhi = (GEMM_ID == 1) ? g_W1hi : g_W2hi;
    const __nv_bfloat16* Blo = (GEMM_ID == 1) ? g_W1lo : g_W2lo;

    float acc[4][4][4];
#pragma unroll
    for (int i = 0; i < 4; i++)
#pragma unroll
        for (int j = 0; j < 4; j++)
#pragma unroll
            for (int k = 0; k < 4; k++) acc[i][j][k] = 0.f;

    auto load_stage = [&](int s) {
        const int k0 = s * 32;
        const uint32_t st = sb + (s & 1) * STAGE_SZ;
#pragma unroll
        for (int i = 0; i < 2; i++) {
            int idx = tid + i * 256;
            int r = idx >> 2, c = idx & 3;
            uint32_t so = (uint32_t)r * 80 + c * 16;
            size_t ga = (size_t)(m0 + r) * DIMK + k0 + c * 8;
            size_t gb = (size_t)(n0 + r) * DIMK + k0 + c * 8;
            cp16(st + so,                Ahi + ga);
            cp16(st + TILE_SZ + so,      Alo + ga);
            cp16(st + 2 * TILE_SZ + so,  Bhi + gb);
            cp16(st + 3 * TILE_SZ + so,  Blo + gb);
        }
        CP_COMMIT();
    };

    load_stage(0);

#pragma unroll 1
    for (int s = 0; s < 16; s++) {
        if (s < 15) {
            load_stage(s + 1);
            CP_WAIT(1);
        } else {
            CP_WAIT(0);
        }
        __syncthreads();
        const uint32_t st = sb + (s & 1) * STAGE_SZ;
        const uint32_t aH = st, aL = st + TILE_SZ;
        const uint32_t bH = st + 2 * TILE_SZ, bL = st + 3 * TILE_SZ;

#pragma unroll
        for (int kk = 0; kk < 2; kk++) {
            uint32_t ah[4][4], al[4][4];
            {
                const int row = warp_m * 64 + (lane & 15);
                const int kc = kk * 16 + (lane >> 4) * 8;
#pragma unroll
                for (int mt = 0; mt < 4; mt++) {
                    uint32_t off = (uint32_t)(row + mt * 16) * 80 + kc * 2;
                    LDSM4(ah[mt], aH + off);
                    LDSM4(al[mt], aL + off);
                }
            }
            const int grp = lane >> 3;
            const int brow = warp_n * 32 + ((grp & 2) << 2) + (lane & 7);
            const int bk = kk * 16 + (grp & 1) * 8;
#pragma unroll
            for (int np = 0; np < 2; np++) {
                uint32_t bh4[4], bl4[4];
                uint32_t off = (uint32_t)(brow + np * 16) * 80 + bk * 2;
                LDSM4(bh4, bH + off);
                LDSM4(bl4, bL + off);
#pragma unroll
                for (int half = 0; half < 2; half++) {
                    const int nt = np * 2 + half;
                    uint32_t bhf[2] = {bh4[half * 2], bh4[half * 2 + 1]};
                    uint32_t blf[2] = {bl4[half * 2], bl4[half * 2 + 1]};
#pragma unroll
                    for (int mt = 0; mt < 4; mt++) {
                        mma16816(acc[mt][nt], ah[mt], bhf);
                        mma16816(acc[mt][nt], al[mt], bhf);
                        mma16816(acc[mt][nt], ah[mt], blf);
                    }
                }
            }
        }
        __syncthreads();
    }

    // ---------------- epilogue ----------------
    const int r0 = lane >> 2;
    const int c0 = (lane & 3) * 2;
#pragma unroll
    for (int mt = 0; mt < 4; mt++) {
#pragma unroll
        for (int nt = 0; nt < 4; nt++) {
            const int col = n0 + warp_n * 32 + nt * 8 + c0;
#pragma unroll
            for (int ri = 0; ri < 2; ri++) {
                const int m = m0 + warp_m * 64 + mt * 16 + r0 + ri * 8;
                float v0 = acc[mt][nt][ri * 2];
                float v1 = acc[mt][nt][ri * 2 + 1];
                if (GEMM_ID == 1) {
                    const int which = col >> 9;
                    const int h = (col >> 6) & 7;
                    const int dd = col & 63;
                    float* dst = (which == 0) ? g_Q : (which == 1) ? g_K : g_V;
                    if (which < 2) {
                        v0 = (v0 > 0.f) ? v0 + 1.f : expf(v0);
                        v1 = (v1 > 0.f) ? v1 + 1.f : expf(v1);
                    }
                    const int b_ = m >> 12, n_ = m & 4095;
                    *(float2*)(dst + ((size_t)(b_ * NH + h) * NN + n_) * HD + dd) =
                        make_float2(v0, v1);
                } else {
                    *(float2*)(outp + (size_t)m * INNER + col) =
                        make_float2(v0 + __ldg(bias + col), v1 + __ldg(bias + col + 1));
                }
            }
        }
    }
}

// ---------------- kv partials ----------------
__global__ __launch_bounds__(256) void k_kv() {
    const int bh = blockIdx.x;
    const int chunk = blockIdx.y;
    const size_t base = ((size_t)bh * NN + (size_t)chunk * (NN / 8)) * HD;
    const float* Kp = g_K + base;
    const float* Vp = g_V + base;
    __shared__ float Ks[32][64];
    __shared__ float Vs[32][64];
    const int tid = threadIdx.x;
    const int td = (tid >> 4) * 4;
    const int te = (tid & 15) * 4;

    float acc[4][4];
#pragma unroll
    for (int i = 0; i < 4; i++)
#pragma unroll
        for (int j = 0; j < 4; j++) acc[i][j] = 0.f;
    float ks[4] = {0.f, 0.f, 0.f, 0.f};
    const bool do_ks = (te == 0);

    for (int nt = 0; nt < NN / 8; nt += 32) {
#pragma unroll
        for (int i = 0; i < 2; i++) {
            int idx = tid + i * 256;
            int r = idx >> 4, c = (idx & 15) * 4;
            *(float4*)&Ks[r][c] = *(const float4*)(Kp + (size_t)(nt + r) * HD + c);
            *(float4*)&Vs[r][c] = *(const float4*)(Vp + (size_t)(nt + r) * HD + c);
        }
        __syncthreads();
#pragma unroll 8
        for (int n = 0; n < 32; n++) {
            float4 kk = *(const float4*)&Ks[n][td];
            float4 vv = *(const float4*)&Vs[n][te];
            float ka[4] = {kk.x, kk.y, kk.z, kk.w};
            float va[4] = {vv.x, vv.y, vv.z, vv.w};
#pragma unroll
            for (int i = 0; i < 4; i++)
#pragma unroll
                for (int j = 0; j < 4; j++)
                    acc[i][j] = fmaf(ka[i], va[j], acc[i][j]);
            if (do_ks) {
                ks[0] += ka[0]; ks[1] += ka[1]; ks[2] += ka[2]; ks[3] += ka[3];
            }
        }
        __syncthreads();
    }

    float* kvp = g_kvp[chunk] + (size_t)bh * HD * HD;
#pragma unroll
    for (int i = 0; i < 4; i++)
        *(float4*)(kvp + (td + i) * HD + te) =
            make_float4(acc[i][0], acc[i][1], acc[i][2], acc[i][3]);
    if (do_ks)
        *(float4*)(g_ksp[chunk] + bh * HD + td) = make_float4(ks[0], ks[1], ks[2], ks[3]);
}

__global__ void k_reduce() {
    int i = blockIdx.x * 256 + threadIdx.x;
    float s = 0.f;
#pragma unroll
    for (int p = 0; p < 8; p++) s += g_kvp[p][i];
    g_kv[i] = s;
    if (i < BHH * HD) {
        float t = 0.f;
#pragma unroll
        for (int p = 0; p < 8; p++) t += g_ksp[p][i];
        g_ksum[i] = t;
    }
}

// ---------------- attn: float4-blocked, bf16 hi/lo output ----------------
__global__ __launch_bounds__(256) void k_attn() {
    const int bh = blockIdx.x;
    const int nt = blockIdx.y;
    __shared__ float KVs[64][68];
    __shared__ float Qs[64][68];
    __shared__ float KS[64];
    const int tid = threadIdx.x;
    const float* kvp = g_kv + (size_t)bh * HD * HD;
    const float* Qp = g_Q + ((size_t)bh * NN + nt * 64) * HD;
#pragma unroll
    for (int i = 0; i < 4; i++) {
        int idx = tid + i * 256;
        int r = idx >> 4, c = (idx & 15) * 4;
        *(float4*)&KVs[r][c] = *(const float4*)(kvp + r * HD + c);
        *(float4*)&Qs[r][c] = *(const float4*)(Qp + (size_t)r * HD + c);
    }
    if (tid < 64) KS[tid] = g_ksum[bh * HD + tid];
    __syncthreads();

    const int te = (tid & 15) * 4;
    const int tn = (tid >> 4) * 4;
    float acc[4][4];
#pragma unroll
    for (int i = 0; i < 4; i++)
#pragma unroll
        for (int j = 0; j < 4; j++) acc[i][j] = 0.f;
    float dot[4] = {0.f, 0.f, 0.f, 0.f};

#pragma unroll 4
    for (int d4 = 0; d4 < 64; d4 += 4) {
        float4 ks4 = *(const float4*)&KS[d4];
        float4 q4[4], kv[4];
#pragma unroll
        for (int i = 0; i < 4; i++) q4[i] = *(const float4*)&Qs[tn + i][d4];
#pragma unroll
        for (int j = 0; j < 4; j++) kv[j] = *(const float4*)&KVs[d4 + j][te];
#pragma unroll
        for (int i = 0; i < 4; i++) {
            dot[i] = fmaf(q4[i].x, ks4.x, dot[i]);
            dot[i] = fmaf(q4[i].y, ks4.y, dot[i]);
            dot[i] = fmaf(q4[i].z, ks4.z, dot[i]);
            dot[i] = fmaf(q4[i].w, ks4.w, dot[i]);
            acc[i][0] = fmaf(q4[i].x, kv[0].x, acc[i][0]);
            acc[i][1] = fmaf(q4[i].x, kv[0].y, acc[i][1]);
            acc[i][2] = fmaf(q4[i].x, kv[0].z, acc[i][2]);
            acc[i][3] = fmaf(q4[i].x, kv[0].w, acc[i][3]);
            acc[i][0] = fmaf(q4[i].y, kv[1].x, acc[i][0]);
            acc[i][1] = fmaf(q4[i].y, kv[1].y, acc[i][1]);
            acc[i][2] = fmaf(q4[i].y, kv[1].z, acc[i][2]);
            acc[i][3] = fmaf(q4[i].y, kv[1].w, acc[i][3]);
            acc[i][0] = fmaf(q4[i].z, kv[2].x, acc[i][0]);
            acc[i][1] = fmaf(q4[i].z, kv[2].y, acc[i][1]);
            acc[i][2] = fmaf(q4[i].z, kv[2].z, acc[i][2]);
            acc[i][3] = fmaf(q4[i].z, kv[2].w, acc[i][3]);
            acc[i][0] = fmaf(q4[i].w, kv[3].x, acc[i][0]);
            acc[i][1] = fmaf(q4[i].w, kv[3].y, acc[i][1]);
            acc[i][2] = fmaf(q4[i].w, kv[3].z, acc[i][2]);
            acc[i][3] = fmaf(q4[i].w, kv[3].w, acc[i][3]);
        }
    }
    const int b_ = bh >> 3, h = bh & 7;
#pragma unroll
    for (int i = 0; i < 4; i++) {
        float z = 1.f / fmaxf(dot[i], 1e-4f);
        int n = nt * 64 + tn + i;
        size_t off = ((size_t)(b_ * NN + n)) * INNER + h * HD + te;
        float v[4];
#pragma unroll
        for (int j = 0; j < 4; j++) v[j] = acc[i][j] * z;
        __nv_bfloat16 hh[4], ll[4];
#pragma unroll
        for (int j = 0; j < 4; j++) {
            hh[j] = __float2bfloat16(v[j]);
            ll[j] = __float2bfloat16(v[j] - __bfloat162float(hh[j]));
        }
        uint2 H, L;
        H.x = (uint32_t)__bfloat16_as_ushort(hh[0]) | ((uint32_t)__bfloat16_as_ushort(hh[1]) << 16);
        H.y = (uint32_t)__bfloat16_as_ushort(hh[2]) | ((uint32_t)__bfloat16_as_ushort(hh[3]) << 16);
        L.x = (uint32_t)__bfloat16_as_ushort(ll[0]) | ((uint32_t)__bfloat16_as_ushort(ll[1]) << 16);
        L.y = (uint32_t)__bfloat16_as_ushort(ll[2]) | ((uint32_t)__bfloat16_as_ushort(ll[3]) << 16);
        *(uint2*)(g_AThi + off) = H;
        *(uint2*)(g_ATlo + off) = L;
    }
}

// ---------------- launch ----------------
extern "C" void kernel_launch(void* const* d_in, const int* in_sizes, int n_in,
                              void* d_out, int out_size) {
    const float* x = (const float*)d_in[0];
    const float* W_qkv = (const float*)d_in[1];
    const float* W_out = (const float*)d_in[2];
    const float* b_out = (const float*)d_in[3];
    float* out = (float*)d_out;

    static int attr_done = 0;
    if (!attr_done) {
        cudaFuncSetAttribute((const void*)k_gemm_mma<1>,
                             cudaFuncAttributeMaxDynamicSharedMemorySize, SMEM_T);
        cudaFuncSetAttribute((const void*)k_gemm_mma<2>,
                             cudaFuncAttributeMaxDynamicSharedMemorySize, SMEM_T);
        attr_done = 1;
    }

    k_convert<<<(MTOT * DIMK / 4) / 256, 256>>>((const float4*)x, 0, MTOT * DIMK / 4);
    k_convert<<<(1536 * DIMK / 4) / 256, 256>>>((const float4*)W_qkv, 1, 1536 * DIMK / 4);
    k_convert<<<(INNER * INNER / 4) / 256, 256>>>((const float4*)W_out, 2, INNER * INNER / 4);

    dim3 g1(1536 / 128, MTOT / 128);   // x = n-blocks, y = m-blocks
    k_gemm_mma<1><<<g1, 256, SMEM_T>>>(nullptr, nullptr);

    dim3 g2(BHH, 8);
    k_kv<<<g2, 256>>>();
    k_reduce<<<(BHH * HD * HD) / 256, 256>>>();

    dim3 g3(BHH, NN / 64);
    k_attn<<<g3, 256>>>();

    dim3 g4(INNER / 128, MTOT / 128);  // x = n-blocks, y = m-blocks
    k_gemm_mma<2><<<g4, 256, SMEM_T>>>(b_out, out);
}

// round 5
// speedup vs baseline: 3.1219x; 1.2189x over previous
#include <cuda_runtime.h>
#include <cuda_fp16.h>
#include <math.h>
#include <stdint.h>

#define BB    16
#define NN    4096
#define DIMK  512
#define NH    8
#define HD    64
#define INNER 512
#define MTOT  (BB * NN)   // 65536
#define BHH   (BB * NH)   // 128

// ---------------- scratch (static device globals) ----------------
__device__ __align__(256) float g_Q[(size_t)BHH * NN * HD];
__device__ __align__(256) float g_K[(size_t)BHH * NN * HD];
__device__ __align__(256) float g_V[(size_t)BHH * NN * HD];
__device__ __align__(256) __half g_Xhi[(size_t)MTOT * DIMK];
__device__ __align__(256) __half g_Xlo[(size_t)MTOT * DIMK];
__device__ __align__(256) __half g_AThi[(size_t)MTOT * INNER];
__device__ __align__(256) __half g_ATlo[(size_t)MTOT * INNER];
__device__ __align__(256) __half g_W1hi[1536 * DIMK];
__device__ __align__(256) __half g_W2hi[INNER * INNER];
__device__ float g_kvp[8][BHH * HD * HD];
__device__ float g_ksp[8][BHH * HD];
__device__ float g_kv[BHH * HD * HD];
__device__ float g_ksum[BHH * HD];

// ---------------- helpers ----------------
__device__ __forceinline__ uint32_t smem_u32(const void* p) {
    uint32_t a;
    asm("{ .reg .u64 t; cvta.to.shared.u64 t, %1; cvt.u32.u64 %0, t; }" : "=r"(a) : "l"(p));
    return a;
}
__device__ __forceinline__ void cp16(uint32_t dst, const void* src) {
    asm volatile("cp.async.cg.shared.global [%0], [%1], 16;" ::
                 "r"(dst), "l"(__cvta_generic_to_global(src)) : "memory");
}
#define CP_COMMIT() asm volatile("cp.async.commit_group;" ::: "memory")
#define CP_WAIT(n)  asm volatile("cp.async.wait_group %0;" :: "n"(n) : "memory")

#define LDSM4(R, A)                                                          \
    asm volatile("ldmatrix.sync.aligned.m8n8.x4.shared.b16 {%0,%1,%2,%3}, [%4];" \
                 : "=r"((R)[0]), "=r"((R)[1]), "=r"((R)[2]), "=r"((R)[3])    \
                 : "r"(A))

__device__ __forceinline__ void mma16816(float* c, const uint32_t* a, const uint32_t* b) {
    asm volatile(
        "mma.sync.aligned.m16n8k16.row.col.f32.f16.f16.f32 "
        "{%0,%1,%2,%3}, {%4,%5,%6,%7}, {%8,%9}, {%0,%1,%2,%3};"
        : "+f"(c[0]), "+f"(c[1]), "+f"(c[2]), "+f"(c[3])
        : "r"(a[0]), "r"(a[1]), "r"(a[2]), "r"(a[3]), "r"(b[0]), "r"(b[1]));
}

__device__ __forceinline__ uint32_t pack2h(float a, float b) {
    __half ha = __float2half_rn(a), hb = __float2half_rn(b);
    return (uint32_t)__half_as_ushort(ha) | ((uint32_t)__half_as_ushort(hb) << 16);
}

// ---------------- convert fp32 -> fp16 hi/lo ----------------
// which: 0 = X (hi+lo), 1 = W1 (hi only), 2 = W2 (hi only)
__global__ void k_convert(const float4* __restrict__ src, int which, int n4) {
    int i = blockIdx.x * 256 + threadIdx.x;
    if (i >= n4) return;
    float4 v = src[i];
    __half h0 = __float2half_rn(v.x), h1 = __float2half_rn(v.y);
    __half h2 = __float2half_rn(v.z), h3 = __float2half_rn(v.w);
    uint2 H;
    H.x = (uint32_t)__half_as_ushort(h0) | ((uint32_t)__half_as_ushort(h1) << 16);
    H.y = (uint32_t)__half_as_ushort(h2) | ((uint32_t)__half_as_ushort(h3) << 16);
    if (which == 0) {
        ((uint2*)g_Xhi)[i] = H;
        __half l0 = __float2half_rn(v.x - __half2float(h0));
        __half l1 = __float2half_rn(v.y - __half2float(h1));
        __half l2 = __float2half_rn(v.z - __half2float(h2));
        __half l3 = __float2half_rn(v.w - __half2float(h3));
        uint2 L;
        L.x = (uint32_t)__half_as_ushort(l0) | ((uint32_t)__half_as_ushort(l1) << 16);
        L.y = (uint32_t)__half_as_ushort(l2) | ((uint32_t)__half_as_ushort(l3) << 16);
        ((uint2*)g_Xlo)[i] = L;
    } else if (which == 1) {
        ((uint2*)g_W1hi)[i] = H;
    } else {
        ((uint2*)g_W2hi)[i] = H;
    }
}

// ---------------- 2-term split-fp16 GEMM on mma.sync ----------------
// C[m][n] = sum_k A[m][k]*B[n][k] with A = Ahi+Alo (exact), B = Bhi (fp16).
// K=512, BLK 128x128x32, 3-stage cp.async, 2 CTAs/SM.
// grid.x = n-blocks (B L2-resident, A streamed once).
#define TILE_SZ 10240            // 128 rows * 80B
#define STAGE_SZ (3 * TILE_SZ)   // Ahi, Alo, Bhi = 30720
#define SMEM_T (3 * STAGE_SZ)    // 92160

template <int GEMM_ID>
__global__ __launch_bounds__(256, 2) void k_gemm_mma(const float* __restrict__ bias,
                                                     float* __restrict__ outp) {
    extern __shared__ char smem[];
    const uint32_t sb = smem_u32(smem);
    const int tid = threadIdx.x;
    const int lane = tid & 31;
    const int wid = tid >> 5;
    const int warp_m = wid >> 2;  // 0..1
    const int warp_n = wid & 3;   // 0..3
    const int m0 = blockIdx.y * 128;
    const int n0 = blockIdx.x * 128;

    const __half* Ahi = (GEMM_ID == 1) ? g_Xhi : g_AThi;
    const __half* Alo = (GEMM_ID == 1) ? g_Xlo : g_ATlo;
    const __half* Bhi = (GEMM_ID == 1) ? g_W1hi : g_W2hi;

    float acc[4][4][4];
#pragma unroll
    for (int i = 0; i < 4; i++)
#pragma unroll
        for (int j = 0; j < 4; j++)
#pragma unroll
            for (int k = 0; k < 4; k++) acc[i][j][k] = 0.f;

    auto load_stage = [&](int s) {
        const int k0 = s * 32;
        const uint32_t st = sb + (s % 3) * STAGE_SZ;
#pragma unroll
        for (int i = 0; i < 2; i++) {
            int idx = tid + i * 256;
            int r = idx >> 2, c = idx & 3;
            uint32_t so = (uint32_t)r * 80 + c * 16;
            size_t ga = (size_t)(m0 + r) * DIMK + k0 + c * 8;
            size_t gb = (size_t)(n0 + r) * DIMK + k0 + c * 8;
            cp16(st + so,               Ahi + ga);
            cp16(st + TILE_SZ + so,     Alo + ga);
            cp16(st + 2 * TILE_SZ + so, Bhi + gb);
        }
        CP_COMMIT();
    };

    load_stage(0);
    load_stage(1);

#pragma unroll 1
    for (int s = 0; s < 16; s++) {
        if (s < 14) {
            load_stage(s + 2);
            CP_WAIT(2);
        } else if (s == 14) {
            CP_WAIT(1);
        } else {
            CP_WAIT(0);
        }
        __syncthreads();
        const uint32_t st = sb + (s % 3) * STAGE_SZ;
        const uint32_t aH = st, aL = st + TILE_SZ;
        const uint32_t bH = st + 2 * TILE_SZ;

#pragma unroll
        for (int kk = 0; kk < 2; kk++) {
            uint32_t ah[4][4], al[4][4];
            {
                const int row = warp_m * 64 + (lane & 15);
                const int kc = kk * 16 + (lane >> 4) * 8;
#pragma unroll
                for (int mt = 0; mt < 4; mt++) {
                    uint32_t off = (uint32_t)(row + mt * 16) * 80 + kc * 2;
                    LDSM4(ah[mt], aH + off);
                    LDSM4(al[mt], aL + off);
                }
            }
            const int grp = lane >> 3;
            const int brow = warp_n * 32 + ((grp & 2) << 2) + (lane & 7);
            const int bk = kk * 16 + (grp & 1) * 8;
#pragma unroll
            for (int np = 0; np < 2; np++) {
                uint32_t bh4[4];
                uint32_t off = (uint32_t)(brow + np * 16) * 80 + bk * 2;
                LDSM4(bh4, bH + off);
#pragma unroll
                for (int half = 0; half < 2; half++) {
                    const int nt = np * 2 + half;
                    uint32_t bhf[2] = {bh4[half * 2], bh4[half * 2 + 1]};
#pragma unroll
                    for (int mt = 0; mt < 4; mt++) {
                        mma16816(acc[mt][nt], ah[mt], bhf);
                        mma16816(acc[mt][nt], al[mt], bhf);
                    }
                }
            }
        }
        __syncthreads();
    }

    // ---------------- epilogue ----------------
    const int r0 = lane >> 2;
    const int c0 = (lane & 3) * 2;
#pragma unroll
    for (int mt = 0; mt < 4; mt++) {
#pragma unroll
        for (int nt = 0; nt < 4; nt++) {
            const int col = n0 + warp_n * 32 + nt * 8 + c0;
#pragma unroll
            for (int ri = 0; ri < 2; ri++) {
                const int m = m0 + warp_m * 64 + mt * 16 + r0 + ri * 8;
                float v0 = acc[mt][nt][ri * 2];
                float v1 = acc[mt][nt][ri * 2 + 1];
                if (GEMM_ID == 1) {
                    const int which = col >> 9;
                    const int h = (col >> 6) & 7;
                    const int dd = col & 63;
                    float* dst = (which == 0) ? g_Q : (which == 1) ? g_K : g_V;
                    if (which < 2) {
                        v0 = (v0 > 0.f) ? v0 + 1.f : expf(v0);
                        v1 = (v1 > 0.f) ? v1 + 1.f : expf(v1);
                    }
                    const int b_ = m >> 12, n_ = m & 4095;
                    *(float2*)(dst + ((size_t)(b_ * NH + h) * NN + n_) * HD + dd) =
                        make_float2(v0, v1);
                } else {
                    *(float2*)(outp + (size_t)m * INNER + col) =
                        make_float2(v0 + __ldg(bias + col), v1 + __ldg(bias + col + 1));
                }
            }
        }
    }
}

// ---------------- kv partials ----------------
__global__ __launch_bounds__(256) void k_kv() {
    const int bh = blockIdx.x;
    const int chunk = blockIdx.y;
    const size_t base = ((size_t)bh * NN + (size_t)chunk * (NN / 8)) * HD;
    const float* Kp = g_K + base;
    const float* Vp = g_V + base;
    __shared__ float Ks[32][64];
    __shared__ float Vs[32][64];
    const int tid = threadIdx.x;
    const int td = (tid >> 4) * 4;
    const int te = (tid & 15) * 4;

    float acc[4][4];
#pragma unroll
    for (int i = 0; i < 4; i++)
#pragma unroll
        for (int j = 0; j < 4; j++) acc[i][j] = 0.f;
    float ks[4] = {0.f, 0.f, 0.f, 0.f};
    const bool do_ks = (te == 0);

    for (int nt = 0; nt < NN / 8; nt += 32) {
#pragma unroll
        for (int i = 0; i < 2; i++) {
            int idx = tid + i * 256;
            int r = idx >> 4, c = (idx & 15) * 4;
            *(float4*)&Ks[r][c] = *(const float4*)(Kp + (size_t)(nt + r) * HD + c);
            *(float4*)&Vs[r][c] = *(const float4*)(Vp + (size_t)(nt + r) * HD + c);
        }
        __syncthreads();
#pragma unroll 8
        for (int n = 0; n < 32; n++) {
            float4 kk = *(const float4*)&Ks[n][td];
            float4 vv = *(const float4*)&Vs[n][te];
            float ka[4] = {kk.x, kk.y, kk.z, kk.w};
            float va[4] = {vv.x, vv.y, vv.z, vv.w};
#pragma unroll
            for (int i = 0; i < 4; i++)
#pragma unroll
                for (int j = 0; j < 4; j++)
                    acc[i][j] = fmaf(ka[i], va[j], acc[i][j]);
            if (do_ks) {
                ks[0] += ka[0]; ks[1] += ka[1]; ks[2] += ka[2]; ks[3] += ka[3];
            }
        }
        __syncthreads();
    }

    float* kvp = g_kvp[chunk] + (size_t)bh * HD * HD;
#pragma unroll
    for (int i = 0; i < 4; i++)
        *(float4*)(kvp + (td + i) * HD + te) =
            make_float4(acc[i][0], acc[i][1], acc[i][2], acc[i][3]);
    if (do_ks)
        *(float4*)(g_ksp[chunk] + bh * HD + td) = make_float4(ks[0], ks[1], ks[2], ks[3]);
}

__global__ void k_reduce() {
    int i = blockIdx.x * 256 + threadIdx.x;
    float s = 0.f;
#pragma unroll
    for (int p = 0; p < 8; p++) s += g_kvp[p][i];
    g_kv[i] = s;
    if (i < BHH * HD) {
        float t = 0.f;
#pragma unroll
        for (int p = 0; p < 8; p++) t += g_ksp[p][i];
        g_ksum[i] = t;
    }
}

// ---------------- attn: float4-blocked, fp16 hi/lo output ----------------
__global__ __launch_bounds__(256) void k_attn() {
    const int bh = blockIdx.x;
    const int nt = blockIdx.y;
    __shared__ float KVs[64][68];
    __shared__ float Qs[64][68];
    __shared__ float KS[64];
    const int tid = threadIdx.x;
    const float* kvp = g_kv + (size_t)bh * HD * HD;
    const float* Qp = g_Q + ((size_t)bh * NN + nt * 64) * HD;
#pragma unroll
    for (int i = 0; i < 4; i++) {
        int idx = tid + i * 256;
        int r = idx >> 4, c = (idx & 15) * 4;
        *(float4*)&KVs[r][c] = *(const float4*)(kvp + r * HD + c);
        *(float4*)&Qs[r][c] = *(const float4*)(Qp + (size_t)r * HD + c);
    }
    if (tid < 64) KS[tid] = g_ksum[bh * HD + tid];
    __syncthreads();

    const int te = (tid & 15) * 4;
    const int tn = (tid >> 4) * 4;
    float acc[4][4];
#pragma unroll
    for (int i = 0; i < 4; i++)
#pragma unroll
        for (int j = 0; j < 4; j++) acc[i][j] = 0.f;
    float dot[4] = {0.f, 0.f, 0.f, 0.f};

#pragma unroll 4
    for (int d4 = 0; d4 < 64; d4 += 4) {
        float4 ks4 = *(const float4*)&KS[d4];
        float4 q4[4], kv[4];
#pragma unroll
        for (int i = 0; i < 4; i++) q4[i] = *(const float4*)&Qs[tn + i][d4];
#pragma unroll
        for (int j = 0; j < 4; j++) kv[j] = *(const float4*)&KVs[d4 + j][te];
#pragma unroll
        for (int i = 0; i < 4; i++) {
            dot[i] = fmaf(q4[i].x, ks4.x, dot[i]);
            dot[i] = fmaf(q4[i].y, ks4.y, dot[i]);
            dot[i] = fmaf(q4[i].z, ks4.z, dot[i]);
            dot[i] = fmaf(q4[i].w, ks4.w, dot[i]);
            acc[i][0] = fmaf(q4[i].x, kv[0].x, acc[i][0]);
            acc[i][1] = fmaf(q4[i].x, kv[0].y, acc[i][1]);
            acc[i][2] = fmaf(q4[i].x, kv[0].z, acc[i][2]);
            acc[i][3] = fmaf(q4[i].x, kv[0].w, acc[i][3]);
            acc[i][0] = fmaf(q4[i].y, kv[1].x, acc[i][0]);
            acc[i][1] = fmaf(q4[i].y, kv[1].y, acc[i][1]);
            acc[i][2] = fmaf(q4[i].y, kv[1].z, acc[i][2]);
            acc[i][3] = fmaf(q4[i].y, kv[1].w, acc[i][3]);
            acc[i][0] = fmaf(q4[i].z, kv[2].x, acc[i][0]);
            acc[i][1] = fmaf(q4[i].z, kv[2].y, acc[i][1]);
            acc[i][2] = fmaf(q4[i].z, kv[2].z, acc[i][2]);
            acc[i][3] = fmaf(q4[i].z, kv[2].w, acc[i][3]);
            acc[i][0] = fmaf(q4[i].w, kv[3].x, acc[i][0]);
            acc[i][1] = fmaf(q4[i].w, kv[3].y, acc[i][1]);
            acc[i][2] = fmaf(q4[i].w, kv[3].z, acc[i][2]);
            acc[i][3] = fmaf(q4[i].w, kv[3].w, acc[i][3]);
        }
    }
    const int b_ = bh >> 3, h = bh & 7;
#pragma unroll
    for (int i = 0; i < 4; i++) {
        float z = 1.f / fmaxf(dot[i], 1e-4f);
        int n = nt * 64 + tn + i;
        size_t off = ((size_t)(b_ * NN + n)) * INNER + h * HD + te;
        float v[4];
#pragma unroll
        for (int j = 0; j < 4; j++) v[j] = acc[i][j] * z;
        __half hh[4], ll[4];
#pragma unroll
        for (int j = 0; j < 4; j++) {
            hh[j] = __float2half_rn(v[j]);
            ll[j] = __float2half_rn(v[j] - __half2float(hh[j]));
        }
        uint2 H, L;
        H.x = (uint32_t)__half_as_ushort(hh[0]) | ((uint32_t)__half_as_ushort(hh[1]) << 16);
        H.y = (uint32_t)__half_as_ushort(hh[2]) | ((uint32_t)__half_as_ushort(hh[3]) << 16);
        L.x = (uint32_t)__half_as_ushort(ll[0]) | ((uint32_t)__half_as_ushort(ll[1]) << 16);
        L.y = (uint32_t)__half_as_ushort(ll[2]) | ((uint32_t)__half_as_ushort(ll[3]) << 16);
        *(uint2*)(g_AThi + off) = H;
        *(uint2*)(g_ATlo + off) = L;
    }
}

// ---------------- launch ----------------
extern "C" void kernel_launch(void* const* d_in, const int* in_sizes, int n_in,
                              void* d_out, int out_size) {
    const float* x = (const float*)d_in[0];
    const float* W_qkv = (const float*)d_in[1];
    const float* W_out = (const float*)d_in[2];
    const float* b_out = (const float*)d_in[3];
    float* out = (float*)d_out;

    static int attr_done = 0;
    if (!attr_done) {
        cudaFuncSetAttribute((const void*)k_gemm_mma<1>,
                             cudaFuncAttributeMaxDynamicSharedMemorySize, SMEM_T);
        cudaFuncSetAttribute((const void*)k_gemm_mma<2>,
                             cudaFuncAttributeMaxDynamicSharedMemorySize, SMEM_T);
        attr_done = 1;
    }

    k_convert<<<(MTOT * DIMK / 4) / 256, 256>>>((const float4*)x, 0, MTOT * DIMK / 4);
    k_convert<<<(1536 * DIMK / 4) / 256, 256>>>((const float4*)W_qkv, 1, 1536 * DIMK / 4);
    k_convert<<<(INNER * INNER / 4) / 256, 256>>>((const float4*)W_out, 2, INNER * INNER / 4);

    dim3 g1(1536 / 128, MTOT / 128);   // x = n-blocks, y = m-blocks
    k_gemm_mma<1><<<g1, 256, SMEM_T>>>(nullptr, nullptr);

    dim3 g2(BHH, 8);
    k_kv<<<g2, 256>>>();
    k_reduce<<<(BHH * HD * HD) / 256, 256>>>();

    dim3 g3(BHH, NN / 64);
    k_attn<<<g3, 256>>>();

    dim3 g4(INNER / 128, MTOT / 128);  // x = n-blocks, y = m-blocks
    k_gemm_mma<2><<<g4, 256, SMEM_T>>>(b_out, out);
}

// round 6
// speedup vs baseline: 3.4984x; 1.1206x over previous
#include <cuda_runtime.h>
#include <cuda_fp16.h>
#include <math.h>
#include <stdint.h>

#define BB    16
#define NN    4096
#define DIMK  512
#define NH    8
#define HD    64
#define INNER 512
#define MTOT  (BB * NN)   // 65536
#define BHH   (BB * NH)   // 128

// ---------------- scratch (static device globals) ----------------
__device__ __align__(256) float g_Q[(size_t)BHH * NN * HD];
__device__ __align__(256) float g_K[(size_t)BHH * NN * HD];
__device__ __align__(256) float g_V[(size_t)BHH * NN * HD];
__device__ __align__(256) __half g_Xhi[(size_t)MTOT * DIMK];
__device__ __align__(256) __half g_Xlo[(size_t)MTOT * DIMK];
__device__ __align__(256) __half g_AThi[(size_t)MTOT * INNER];
__device__ __align__(256) __half g_ATlo[(size_t)MTOT * INNER];
__device__ __align__(256) __half g_W1hi[1536 * DIMK];
__device__ __align__(256) __half g_W2hi[INNER * INNER];
__device__ float g_kvp[8][BHH * HD * HD];
__device__ float g_ksp[8][BHH * HD];
__device__ float g_kv[BHH * HD * HD];
__device__ float g_ksum[BHH * HD];

// ---------------- helpers ----------------
__device__ __forceinline__ uint32_t smem_u32(const void* p) {
    uint32_t a;
    asm("{ .reg .u64 t; cvta.to.shared.u64 t, %1; cvt.u32.u64 %0, t; }" : "=r"(a) : "l"(p));
    return a;
}
__device__ __forceinline__ void cp16(uint32_t dst, const void* src) {
    asm volatile("cp.async.cg.shared.global [%0], [%1], 16;" ::
                 "r"(dst), "l"(__cvta_generic_to_global(src)) : "memory");
}
#define CP_COMMIT() asm volatile("cp.async.commit_group;" ::: "memory")
#define CP_WAIT(n)  asm volatile("cp.async.wait_group %0;" :: "n"(n) : "memory")

#define LDSM4(R, A)                                                          \
    asm volatile("ldmatrix.sync.aligned.m8n8.x4.shared.b16 {%0,%1,%2,%3}, [%4];" \
                 : "=r"((R)[0]), "=r"((R)[1]), "=r"((R)[2]), "=r"((R)[3])    \
                 : "r"(A))

__device__ __forceinline__ void mma16816(float* c, const uint32_t* a, const uint32_t* b) {
    asm volatile(
        "mma.sync.aligned.m16n8k16.row.col.f32.f16.f16.f32 "
        "{%0,%1,%2,%3}, {%4,%5,%6,%7}, {%8,%9}, {%0,%1,%2,%3};"
        : "+f"(c[0]), "+f"(c[1]), "+f"(c[2]), "+f"(c[3])
        : "r"(a[0]), "r"(a[1]), "r"(a[2]), "r"(a[3]), "r"(b[0]), "r"(b[1]));
}

// ---------------- convert fp32 -> fp16 hi/lo ----------------
__global__ void k_convert(const float4* __restrict__ src, int which, int n4) {
    int i = blockIdx.x * 256 + threadIdx.x;
    if (i >= n4) return;
    float4 v = src[i];
    __half h0 = __float2half_rn(v.x), h1 = __float2half_rn(v.y);
    __half h2 = __float2half_rn(v.z), h3 = __float2half_rn(v.w);
    uint2 H;
    H.x = (uint32_t)__half_as_ushort(h0) | ((uint32_t)__half_as_ushort(h1) << 16);
    H.y = (uint32_t)__half_as_ushort(h2) | ((uint32_t)__half_as_ushort(h3) << 16);
    if (which == 0) {
        ((uint2*)g_Xhi)[i] = H;
        __half l0 = __float2half_rn(v.x - __half2float(h0));
        __half l1 = __float2half_rn(v.y - __half2float(h1));
        __half l2 = __float2half_rn(v.z - __half2float(h2));
        __half l3 = __float2half_rn(v.w - __half2float(h3));
        uint2 L;
        L.x = (uint32_t)__half_as_ushort(l0) | ((uint32_t)__half_as_ushort(l1) << 16);
        L.y = (uint32_t)__half_as_ushort(l2) | ((uint32_t)__half_as_ushort(l3) << 16);
        ((uint2*)g_Xlo)[i] = L;
    } else if (which == 1) {
        ((uint2*)g_W1hi)[i] = H;
    } else {
        ((uint2*)g_W2hi)[i] = H;
    }
}

// ---------------- 2-term split-fp16 GEMM, warp tile 32x64, k64 stages ----
// C[m][n] = sum_k A[m][k]*B[n][k], A = Ahi+Alo, B = Bhi.
// CTA 128x128xK64, 8 warps as 4(m) x 2(n), 2-stage cp.async, 2 CTAs/SM.
#define ROWB 144                  // 64 halves = 128B data + 16B pad
#define ASZ  (128 * ROWB)         // 18432 per tile
#define STAGE_SZ (3 * ASZ)        // Ahi, Alo, Bhi = 55296
#define SMEM_T (2 * STAGE_SZ)     // 110592

template <int GEMM_ID>
__global__ __launch_bounds__(256, 2) void k_gemm_mma(const float* __restrict__ bias,
                                                     float* __restrict__ outp) {
    extern __shared__ char smem[];
    const uint32_t sb = smem_u32(smem);
    const int tid = threadIdx.x;
    const int lane = tid & 31;
    const int wid = tid >> 5;
    const int warp_m = wid >> 1;  // 0..3 -> 32 rows each
    const int warp_n = wid & 1;   // 0..1 -> 64 cols each
    const int m0 = blockIdx.y * 128;
    const int n0 = blockIdx.x * 128;

    const __half* Ahi = (GEMM_ID == 1) ? g_Xhi : g_AThi;
    const __half* Alo = (GEMM_ID == 1) ? g_Xlo : g_ATlo;
    const __half* Bhi = (GEMM_ID == 1) ? g_W1hi : g_W2hi;

    float acc[2][8][4];
#pragma unroll
    for (int i = 0; i < 2; i++)
#pragma unroll
        for (int j = 0; j < 8; j++)
#pragma unroll
            for (int k = 0; k < 4; k++) acc[i][j][k] = 0.f;

    auto load_stage = [&](int s) {
        const int k0 = s * 64;
        const uint32_t st = sb + (s & 1) * STAGE_SZ;
#pragma unroll
        for (int i = 0; i < 4; i++) {
            int idx = tid + i * 256;         // 0..1023
            int r = idx >> 3, c = idx & 7;
            uint32_t so = (uint32_t)r * ROWB + c * 16;
            size_t ga = (size_t)(m0 + r) * DIMK + k0 + c * 8;
            size_t gb = (size_t)(n0 + r) * DIMK + k0 + c * 8;
            cp16(st + so,           Ahi + ga);
            cp16(st + ASZ + so,     Alo + ga);
            cp16(st + 2 * ASZ + so, Bhi + gb);
        }
        CP_COMMIT();
    };

    load_stage(0);

#pragma unroll 1
    for (int s = 0; s < 8; s++) {
        if (s < 7) {
            load_stage(s + 1);
            CP_WAIT(1);
        } else {
            CP_WAIT(0);
        }
        __syncthreads();
        const uint32_t st = sb + (s & 1) * STAGE_SZ;
        const uint32_t aH = st, aL = st + ASZ, bH = st + 2 * ASZ;

        const int arow = warp_m * 32 + (lane & 15);
        const int grp = lane >> 3;
        const int brow_l = warp_n * 64 + ((grp & 2) << 2) + (lane & 7);

#pragma unroll
        for (int kk = 0; kk < 4; kk++) {
            const int kc = kk * 16 + (lane >> 4) * 8;
            uint32_t ah[2][4], al[2][4];
#pragma unroll
            for (int mt = 0; mt < 2; mt++) {
                uint32_t off = (uint32_t)(arow + mt * 16) * ROWB + kc * 2;
                LDSM4(ah[mt], aH + off);
                LDSM4(al[mt], aL + off);
            }
            const int bk = kk * 16 + (grp & 1) * 8;
            uint32_t bh4[4][4];
#pragma unroll
            for (int np = 0; np < 4; np++) {
                uint32_t off = (uint32_t)(brow_l + np * 16) * ROWB + bk * 2;
                LDSM4(bh4[np], bH + off);
            }
#pragma unroll
            for (int np = 0; np < 4; np++) {
#pragma unroll
                for (int half = 0; half < 2; half++) {
                    const int nt = np * 2 + half;
                    uint32_t bhf[2] = {bh4[np][half * 2], bh4[np][half * 2 + 1]};
#pragma unroll
                    for (int mt = 0; mt < 2; mt++) {
                        mma16816(acc[mt][nt], ah[mt], bhf);
                        mma16816(acc[mt][nt], al[mt], bhf);
                    }
                }
            }
        }
        __syncthreads();
    }

    // ---------------- epilogue ----------------
    const int r0 = lane >> 2;
    const int c0 = (lane & 3) * 2;
#pragma unroll
    for (int mt = 0; mt < 2; mt++) {
#pragma unroll
        for (int nt = 0; nt < 8; nt++) {
            const int col = n0 + warp_n * 64 + nt * 8 + c0;
#pragma unroll
            for (int ri = 0; ri < 2; ri++) {
                const int m = m0 + warp_m * 32 + mt * 16 + r0 + ri * 8;
                float v0 = acc[mt][nt][ri * 2];
                float v1 = acc[mt][nt][ri * 2 + 1];
                if (GEMM_ID == 1) {
                    const int which = col >> 9;
                    const int h = (col >> 6) & 7;
                    const int dd = col & 63;
                    float* dst = (which == 0) ? g_Q : (which == 1) ? g_K : g_V;
                    if (which < 2) {
                        v0 = (v0 > 0.f) ? v0 + 1.f : expf(v0);
                        v1 = (v1 > 0.f) ? v1 + 1.f : expf(v1);
                    }
                    const int b_ = m >> 12, n_ = m & 4095;
                    *(float2*)(dst + ((size_t)(b_ * NH + h) * NN + n_) * HD + dd) =
                        make_float2(v0, v1);
                } else {
                    *(float2*)(outp + (size_t)m * INNER + col) =
                        make_float2(v0 + __ldg(bias + col), v1 + __ldg(bias + col + 1));
                }
            }
        }
    }
}

// ---------------- kv partials ----------------
__global__ __launch_bounds__(256) void k_kv() {
    const int bh = blockIdx.x;
    const int chunk = blockIdx.y;
    const size_t base = ((size_t)bh * NN + (size_t)chunk * (NN / 8)) * HD;
    const float* Kp = g_K + base;
    const float* Vp = g_V + base;
    __shared__ float Ks[32][64];
    __shared__ float Vs[32][64];
    const int tid = threadIdx.x;
    const int td = (tid >> 4) * 4;
    const int te = (tid & 15) * 4;

    float acc[4][4];
#pragma unroll
    for (int i = 0; i < 4; i++)
#pragma unroll
        for (int j = 0; j < 4; j++) acc[i][j] = 0.f;
    float ks[4] = {0.f, 0.f, 0.f, 0.f};
    const bool do_ks = (te == 0);

    for (int nt = 0; nt < NN / 8; nt += 32) {
#pragma unroll
        for (int i = 0; i < 2; i++) {
            int idx = tid + i * 256;
            int r = idx >> 4, c = (idx & 15) * 4;
            *(float4*)&Ks[r][c] = *(const float4*)(Kp + (size_t)(nt + r) * HD + c);
            *(float4*)&Vs[r][c] = *(const float4*)(Vp + (size_t)(nt + r) * HD + c);
        }
        __syncthreads();
#pragma unroll 8
        for (int n = 0; n < 32; n++) {
            float4 kk = *(const float4*)&Ks[n][td];
            float4 vv = *(const float4*)&Vs[n][te];
            float ka[4] = {kk.x, kk.y, kk.z, kk.w};
            float va[4] = {vv.x, vv.y, vv.z, vv.w};
#pragma unroll
            for (int i = 0; i < 4; i++)
#pragma unroll
                for (int j = 0; j < 4; j++)
                    acc[i][j] = fmaf(ka[i], va[j], acc[i][j]);
            if (do_ks) {
                ks[0] += ka[0]; ks[1] += ka[1]; ks[2] += ka[2]; ks[3] += ka[3];
            }
        }
        __syncthreads();
    }

    float* kvp = g_kvp[chunk] + (size_t)bh * HD * HD;
#pragma unroll
    for (int i = 0; i < 4; i++)
        *(float4*)(kvp + (td + i) * HD + te) =
            make_float4(acc[i][0], acc[i][1], acc[i][2], acc[i][3]);
    if (do_ks)
        *(float4*)(g_ksp[chunk] + bh * HD + td) = make_float4(ks[0], ks[1], ks[2], ks[3]);
}

__global__ void k_reduce() {
    int i = blockIdx.x * 256 + threadIdx.x;
    float s = 0.f;
#pragma unroll
    for (int p = 0; p < 8; p++) s += g_kvp[p][i];
    g_kv[i] = s;
    if (i < BHH * HD) {
        float t = 0.f;
#pragma unroll
        for (int p = 0; p < 8; p++) t += g_ksp[p][i];
        g_ksum[i] = t;
    }
}

// ---------------- attn: float4-blocked, fp16 hi/lo output ----------------
__global__ __launch_bounds__(256) void k_attn() {
    const int bh = blockIdx.x;
    const int nt = blockIdx.y;
    __shared__ float KVs[64][68];
    __shared__ float Qs[64][68];
    __shared__ float KS[64];
    const int tid = threadIdx.x;
    const float* kvp = g_kv + (size_t)bh * HD * HD;
    const float* Qp = g_Q + ((size_t)bh * NN + nt * 64) * HD;
#pragma unroll
    for (int i = 0; i < 4; i++) {
        int idx = tid + i * 256;
        int r = idx >> 4, c = (idx & 15) * 4;
        *(float4*)&KVs[r][c] = *(const float4*)(kvp + r * HD + c);
        *(float4*)&Qs[r][c] = *(const float4*)(Qp + (size_t)r * HD + c);
    }
    if (tid < 64) KS[tid] = g_ksum[bh * HD + tid];
    __syncthreads();

    const int te = (tid & 15) * 4;
    const int tn = (tid >> 4) * 4;
    float acc[4][4];
#pragma unroll
    for (int i = 0; i < 4; i++)
#pragma unroll
        for (int j = 0; j < 4; j++) acc[i][j] = 0.f;
    float dot[4] = {0.f, 0.f, 0.f, 0.f};

#pragma unroll 4
    for (int d4 = 0; d4 < 64; d4 += 4) {
        float4 ks4 = *(const float4*)&KS[d4];
        float4 q4[4], kv[4];
#pragma unroll
        for (int i = 0; i < 4; i++) q4[i] = *(const float4*)&Qs[tn + i][d4];
#pragma unroll
        for (int j = 0; j < 4; j++) kv[j] = *(const float4*)&KVs[d4 + j][te];
#pragma unroll
        for (int i = 0; i < 4; i++) {
            dot[i] = fmaf(q4[i].x, ks4.x, dot[i]);
            dot[i] = fmaf(q4[i].y, ks4.y, dot[i]);
            dot[i] = fmaf(q4[i].z, ks4.z, dot[i]);
            dot[i] = fmaf(q4[i].w, ks4.w, dot[i]);
            acc[i][0] = fmaf(q4[i].x, kv[0].x, acc[i][0]);
            acc[i][1] = fmaf(q4[i].x, kv[0].y, acc[i][1]);
            acc[i][2] = fmaf(q4[i].x, kv[0].z, acc[i][2]);
            acc[i][3] = fmaf(q4[i].x, kv[0].w, acc[i][3]);
            acc[i][0] = fmaf(q4[i].y, kv[1].x, acc[i][0]);
            acc[i][1] = fmaf(q4[i].y, kv[1].y, acc[i][1]);
            acc[i][2] = fmaf(q4[i].y, kv[1].z, acc[i][2]);
            acc[i][3] = fmaf(q4[i].y, kv[1].w, acc[i][3]);
            acc[i][0] = fmaf(q4[i].z, kv[2].x, acc[i][0]);
            acc[i][1] = fmaf(q4[i].z, kv[2].y, acc[i][1]);
            acc[i][2] = fmaf(q4[i].z, kv[2].z, acc[i][2]);
            acc[i][3] = fmaf(q4[i].z, kv[2].w, acc[i][3]);
            acc[i][0] = fmaf(q4[i].w, kv[3].x, acc[i][0]);
            acc[i][1] = fmaf(q4[i].w, kv[3].y, acc[i][1]);
            acc[i][2] = fmaf(q4[i].w, kv[3].z, acc[i][2]);
            acc[i][3] = fmaf(q4[i].w, kv[3].w, acc[i][3]);
        }
    }
    const int b_ = bh >> 3, h = bh & 7;
#pragma unroll
    for (int i = 0; i < 4; i++) {
        float z = 1.f / fmaxf(dot[i], 1e-4f);
        int n = nt * 64 + tn + i;
        size_t off = ((size_t)(b_ * NN + n)) * INNER + h * HD + te;
        float v[4];
#pragma unroll
        for (int j = 0; j < 4; j++) v[j] = acc[i][j] * z;
        __half hh[4], ll[4];
#pragma unroll
        for (int j = 0; j < 4; j++) {
            hh[j] = __float2half_rn(v[j]);
            ll[j] = __float2half_rn(v[j] - __half2float(hh[j]));
        }
        uint2 H, L;
        H.x = (uint32_t)__half_as_ushort(hh[0]) | ((uint32_t)__half_as_ushort(hh[1]) << 16);
        H.y = (uint32_t)__half_as_ushort(hh[2]) | ((uint32_t)__half_as_ushort(hh[3]) << 16);
        L.x = (uint32_t)__half_as_ushort(ll[0]) | ((uint32_t)__half_as_ushort(ll[1]) << 16);
        L.y = (uint32_t)__half_as_ushort(ll[2]) | ((uint32_t)__half_as_ushort(ll[3]) << 16);
        *(uint2*)(g_AThi + off) = H;
        *(uint2*)(g_ATlo + off) = L;
    }
}

// ---------------- launch ----------------
extern "C" void kernel_launch(void* const* d_in, const int* in_sizes, int n_in,
                              void* d_out, int out_size) {
    const float* x = (const float*)d_in[0];
    const float* W_qkv = (const float*)d_in[1];
    const float* W_out = (const float*)d_in[2];
    const float* b_out = (const float*)d_in[3];
    float* out = (float*)d_out;

    static int attr_done = 0;
    if (!attr_done) {
        cudaFuncSetAttribute((const void*)k_gemm_mma<1>,
                             cudaFuncAttributeMaxDynamicSharedMemorySize, SMEM_T);
        cudaFuncSetAttribute((const void*)k_gemm_mma<2>,
                             cudaFuncAttributeMaxDynamicSharedMemorySize, SMEM_T);
        attr_done = 1;
    }

    k_convert<<<(MTOT * DIMK / 4) / 256, 256>>>((const float4*)x, 0, MTOT * DIMK / 4);
    k_convert<<<(1536 * DIMK / 4) / 256, 256>>>((const float4*)W_qkv, 1, 1536 * DIMK / 4);
    k_convert<<<(INNER * INNER / 4) / 256, 256>>>((const float4*)W_out, 2, INNER * INNER / 4);

    dim3 g1(1536 / 128, MTOT / 128);   // x = n-blocks, y = m-blocks
    k_gemm_mma<1><<<g1, 256, SMEM_T>>>(nullptr, nullptr);

    dim3 g2(BHH, 8);
    k_kv<<<g2, 256>>>();
    k_reduce<<<(BHH * HD * HD) / 256, 256>>>();

    dim3 g3(BHH, NN / 64);
    k_attn<<<g3, 256>>>();

    dim3 g4(INNER / 128, MTOT / 128);  // x = n-blocks, y = m-blocks
    k_gemm_mma<2><<<g4, 256, SMEM_T>>>(b_out, out);
}

// round 7
// speedup vs baseline: 3.6340x; 1.0388x over previous
#include <cuda_runtime.h>
#include <cuda_fp16.h>
#include <math.h>
#include <stdint.h>

#define BB    16
#define NN    4096
#define DIMK  512
#define NH    8
#define HD    64
#define INNER 512
#define MTOT  (BB * NN)   // 65536
#define BHH   (BB * NH)   // 128

// ---------------- scratch (static device globals) ----------------
__device__ __align__(256) float g_Q[(size_t)BHH * NN * HD];
__device__ __align__(256) float g_K[(size_t)BHH * NN * HD];
__device__ __align__(256) float g_V[(size_t)BHH * NN * HD];
__device__ __align__(256) __half g_X16[(size_t)MTOT * DIMK];
__device__ __align__(256) __half g_AT16[(size_t)MTOT * INNER];
__device__ __align__(256) __half g_W1[1536 * DIMK];
__device__ __align__(256) __half g_W2[INNER * INNER];
__device__ float g_kvp[8][BHH * HD * HD];
__device__ float g_ksp[8][BHH * HD];
__device__ float g_kv[BHH * HD * HD];
__device__ float g_ksum[BHH * HD];

// ---------------- helpers ----------------
__device__ __forceinline__ uint32_t smem_u32(const void* p) {
    uint32_t a;
    asm("{ .reg .u64 t; cvta.to.shared.u64 t, %1; cvt.u32.u64 %0, t; }" : "=r"(a) : "l"(p));
    return a;
}
__device__ __forceinline__ void cp16(uint32_t dst, const void* src) {
    asm volatile("cp.async.cg.shared.global [%0], [%1], 16;" ::
                 "r"(dst), "l"(__cvta_generic_to_global(src)) : "memory");
}
#define CP_COMMIT() asm volatile("cp.async.commit_group;" ::: "memory")
#define CP_WAIT(n)  asm volatile("cp.async.wait_group %0;" :: "n"(n) : "memory")

#define LDSM4(R, A)                                                          \
    asm volatile("ldmatrix.sync.aligned.m8n8.x4.shared.b16 {%0,%1,%2,%3}, [%4];" \
                 : "=r"((R)[0]), "=r"((R)[1]), "=r"((R)[2]), "=r"((R)[3])    \
                 : "r"(A))

__device__ __forceinline__ void mma16816(float* c, const uint32_t* a, const uint32_t* b) {
    asm volatile(
        "mma.sync.aligned.m16n8k16.row.col.f32.f16.f16.f32 "
        "{%0,%1,%2,%3}, {%4,%5,%6,%7}, {%8,%9}, {%0,%1,%2,%3};"
        : "+f"(c[0]), "+f"(c[1]), "+f"(c[2]), "+f"(c[3])
        : "r"(a[0]), "r"(a[1]), "r"(a[2]), "r"(a[3]), "r"(b[0]), "r"(b[1]));
}

// ---------------- convert fp32 -> fp16 ----------------
__global__ void k_convert(const float4* __restrict__ src, int which, int n4) {
    int i = blockIdx.x * 256 + threadIdx.x;
    if (i >= n4) return;
    float4 v = src[i];
    uint2 H;
    H.x = (uint32_t)__half_as_ushort(__float2half_rn(v.x)) |
          ((uint32_t)__half_as_ushort(__float2half_rn(v.y)) << 16);
    H.y = (uint32_t)__half_as_ushort(__float2half_rn(v.z)) |
          ((uint32_t)__half_as_ushort(__float2half_rn(v.w)) << 16);
    uint2* dst = (which == 0) ? (uint2*)g_X16 : (which == 1) ? (uint2*)g_W1 : (uint2*)g_W2;
    dst[i] = H;
}

// ---------------- single-pass fp16 GEMM, warp tile 32x64, k64 stages ----
// C[m][n] = sum_k A[m][k]*B[n][k].
// CTA 128x128xK64, 8 warps as 4(m) x 2(n), 3-stage cp.async, 2 CTAs/SM.
#define ROWB 144                  // 64 halves = 128B data + 16B pad
#define ASZ  (128 * ROWB)         // 18432 per tile
#define STAGE_SZ (2 * ASZ)        // A, B = 36864
#define SMEM_T (3 * STAGE_SZ)     // 110592

template <int GEMM_ID>
__global__ __launch_bounds__(256, 2) void k_gemm_mma(const float* __restrict__ bias,
                                                     float* __restrict__ outp) {
    extern __shared__ char smem[];
    const uint32_t sb = smem_u32(smem);
    const int tid = threadIdx.x;
    const int lane = tid & 31;
    const int wid = tid >> 5;
    const int warp_m = wid >> 1;  // 0..3 -> 32 rows each
    const int warp_n = wid & 1;   // 0..1 -> 64 cols each
    const int m0 = blockIdx.y * 128;
    const int n0 = blockIdx.x * 128;

    const __half* A = (GEMM_ID == 1) ? g_X16 : g_AT16;
    const __half* B = (GEMM_ID == 1) ? g_W1 : g_W2;

    float acc[2][8][4];
#pragma unroll
    for (int i = 0; i < 2; i++)
#pragma unroll
        for (int j = 0; j < 8; j++)
#pragma unroll
            for (int k = 0; k < 4; k++) acc[i][j][k] = 0.f;

    auto load_stage = [&](int s) {
        const int k0 = s * 64;
        const uint32_t st = sb + (s % 3) * STAGE_SZ;
#pragma unroll
        for (int i = 0; i < 4; i++) {
            int idx = tid + i * 256;         // 0..1023
            int r = idx >> 3, c = idx & 7;
            uint32_t so = (uint32_t)r * ROWB + c * 16;
            cp16(st + so,       A + (size_t)(m0 + r) * DIMK + k0 + c * 8);
            cp16(st + ASZ + so, B + (size_t)(n0 + r) * DIMK + k0 + c * 8);
        }
        CP_COMMIT();
    };

    load_stage(0);
    load_stage(1);

#pragma unroll 1
    for (int s = 0; s < 8; s++) {
        if (s < 6) {
            load_stage(s + 2);
            CP_WAIT(2);
        } else if (s == 6) {
            CP_WAIT(1);
        } else {
            CP_WAIT(0);
        }
        __syncthreads();
        const uint32_t st = sb + (s % 3) * STAGE_SZ;
        const uint32_t aT = st, bT = st + ASZ;

        const int arow = warp_m * 32 + (lane & 15);
        const int grp = lane >> 3;
        const int brow_l = warp_n * 64 + ((grp & 2) << 2) + (lane & 7);

#pragma unroll
        for (int kk = 0; kk < 4; kk++) {
            const int kc = kk * 16 + (lane >> 4) * 8;
            uint32_t ah[2][4];
#pragma unroll
            for (int mt = 0; mt < 2; mt++) {
                uint32_t off = (uint32_t)(arow + mt * 16) * ROWB + kc * 2;
                LDSM4(ah[mt], aT + off);
            }
            const int bk = kk * 16 + (grp & 1) * 8;
            uint32_t bh4[4][4];
#pragma unroll
            for (int np = 0; np < 4; np++) {
                uint32_t off = (uint32_t)(brow_l + np * 16) * ROWB + bk * 2;
                LDSM4(bh4[np], bT + off);
            }
#pragma unroll
            for (int np = 0; np < 4; np++) {
#pragma unroll
                for (int half = 0; half < 2; half++) {
                    const int nt = np * 2 + half;
                    uint32_t bhf[2] = {bh4[np][half * 2], bh4[np][half * 2 + 1]};
#pragma unroll
                    for (int mt = 0; mt < 2; mt++)
                        mma16816(acc[mt][nt], ah[mt], bhf);
                }
            }
        }
        __syncthreads();
    }

    // ---------------- epilogue ----------------
    const int r0 = lane >> 2;
    const int c0 = (lane & 3) * 2;
#pragma unroll
    for (int mt = 0; mt < 2; mt++) {
#pragma unroll
        for (int nt = 0; nt < 8; nt++) {
            const int col = n0 + warp_n * 64 + nt * 8 + c0;
#pragma unroll
            for (int ri = 0; ri < 2; ri++) {
                const int m = m0 + warp_m * 32 + mt * 16 + r0 + ri * 8;
                float v0 = acc[mt][nt][ri * 2];
                float v1 = acc[mt][nt][ri * 2 + 1];
                if (GEMM_ID == 1) {
                    const int which = col >> 9;
                    const int h = (col >> 6) & 7;
                    const int dd = col & 63;
                    float* dst = (which == 0) ? g_Q : (which == 1) ? g_K : g_V;
                    if (which < 2) {
                        v0 = (v0 > 0.f) ? v0 + 1.f : expf(v0);
                        v1 = (v1 > 0.f) ? v1 + 1.f : expf(v1);
                    }
                    const int b_ = m >> 12, n_ = m & 4095;
                    *(float2*)(dst + ((size_t)(b_ * NH + h) * NN + n_) * HD + dd) =
                        make_float2(v0, v1);
                } else {
                    *(float2*)(outp + (size_t)m * INNER + col) =
                        make_float2(v0 + __ldg(bias + col), v1 + __ldg(bias + col + 1));
                }
            }
        }
    }
}

// ---------------- kv partials ----------------
__global__ __launch_bounds__(256) void k_kv() {
    const int bh = blockIdx.x;
    const int chunk = blockIdx.y;
    const size_t base = ((size_t)bh * NN + (size_t)chunk * (NN / 8)) * HD;
    const float* Kp = g_K + base;
    const float* Vp = g_V + base;
    __shared__ float Ks[32][64];
    __shared__ float Vs[32][64];
    const int tid = threadIdx.x;
    const int td = (tid >> 4) * 4;
    const int te = (tid & 15) * 4;

    float acc[4][4];
#pragma unroll
    for (int i = 0; i < 4; i++)
#pragma unroll
        for (int j = 0; j < 4; j++) acc[i][j] = 0.f;
    float ks[4] = {0.f, 0.f, 0.f, 0.f};
    const bool do_ks = (te == 0);

    for (int nt = 0; nt < NN / 8; nt += 32) {
#pragma unroll
        for (int i = 0; i < 2; i++) {
            int idx = tid + i * 256;
            int r = idx >> 4, c = (idx & 15) * 4;
            *(float4*)&Ks[r][c] = *(const float4*)(Kp + (size_t)(nt + r) * HD + c);
            *(float4*)&Vs[r][c] = *(const float4*)(Vp + (size_t)(nt + r) * HD + c);
        }
        __syncthreads();
#pragma unroll 8
        for (int n = 0; n < 32; n++) {
            float4 kk = *(const float4*)&Ks[n][td];
            float4 vv = *(const float4*)&Vs[n][te];
            float ka[4] = {kk.x, kk.y, kk.z, kk.w};
            float va[4] = {vv.x, vv.y, vv.z, vv.w};
#pragma unroll
            for (int i = 0; i < 4; i++)
#pragma unroll
                for (int j = 0; j < 4; j++)
                    acc[i][j] = fmaf(ka[i], va[j], acc[i][j]);
            if (do_ks) {
                ks[0] += ka[0]; ks[1] += ka[1]; ks[2] += ka[2]; ks[3] += ka[3];
            }
        }
        __syncthreads();
    }

    float* kvp = g_kvp[chunk] + (size_t)bh * HD * HD;
#pragma unroll
    for (int i = 0; i < 4; i++)
        *(float4*)(kvp + (td + i) * HD + te) =
            make_float4(acc[i][0], acc[i][1], acc[i][2], acc[i][3]);
    if (do_ks)
        *(float4*)(g_ksp[chunk] + bh * HD + td) = make_float4(ks[0], ks[1], ks[2], ks[3]);
}

__global__ void k_reduce() {
    int i = blockIdx.x * 256 + threadIdx.x;
    float s = 0.f;
#pragma unroll
    for (int p = 0; p < 8; p++) s += g_kvp[p][i];
    g_kv[i] = s;
    if (i < BHH * HD) {
        float t = 0.f;
#pragma unroll
        for (int p = 0; p < 8; p++) t += g_ksp[p][i];
        g_ksum[i] = t;
    }
}

// ---------------- attn: float4-blocked, fp16 output ----------------
__global__ __launch_bounds__(256) void k_attn() {
    const int bh = blockIdx.x;
    const int nt = blockIdx.y;
    __shared__ float KVs[64][68];
    __shared__ float Qs[64][68];
    __shared__ float KS[64];
    const int tid = threadIdx.x;
    const float* kvp = g_kv + (size_t)bh * HD * HD;
    const float* Qp = g_Q + ((size_t)bh * NN + nt * 64) * HD;
#pragma unroll
    for (int i = 0; i < 4; i++) {
        int idx = tid + i * 256;
        int r = idx >> 4, c = (idx & 15) * 4;
        *(float4*)&KVs[r][c] = *(const float4*)(kvp + r * HD + c);
        *(float4*)&Qs[r][c] = *(const float4*)(Qp + (size_t)r * HD + c);
    }
    if (tid < 64) KS[tid] = g_ksum[bh * HD + tid];
    __syncthreads();

    const int te = (tid & 15) * 4;
    const int tn = (tid >> 4) * 4;
    float acc[4][4];
#pragma unroll
    for (int i = 0; i < 4; i++)
#pragma unroll
        for (int j = 0; j < 4; j++) acc[i][j] = 0.f;
    float dot[4] = {0.f, 0.f, 0.f, 0.f};

#pragma unroll 4
    for (int d4 = 0; d4 < 64; d4 += 4) {
        float4 ks4 = *(const float4*)&KS[d4];
        float4 q4[4], kv[4];
#pragma unroll
        for (int i = 0; i < 4; i++) q4[i] = *(const float4*)&Qs[tn + i][d4];
#pragma unroll
        for (int j = 0; j < 4; j++) kv[j] = *(const float4*)&KVs[d4 + j][te];
#pragma unroll
        for (int i = 0; i < 4; i++) {
            dot[i] = fmaf(q4[i].x, ks4.x, dot[i]);
            dot[i] = fmaf(q4[i].y, ks4.y, dot[i]);
            dot[i] = fmaf(q4[i].z, ks4.z, dot[i]);
            dot[i] = fmaf(q4[i].w, ks4.w, dot[i]);
            acc[i][0] = fmaf(q4[i].x, kv[0].x, acc[i][0]);
            acc[i][1] = fmaf(q4[i].x, kv[0].y, acc[i][1]);
            acc[i][2] = fmaf(q4[i].x, kv[0].z, acc[i][2]);
            acc[i][3] = fmaf(q4[i].x, kv[0].w, acc[i][3]);
            acc[i][0] = fmaf(q4[i].y, kv[1].x, acc[i][0]);
            acc[i][1] = fmaf(q4[i].y, kv[1].y, acc[i][1]);
            acc[i][2] = fmaf(q4[i].y, kv[1].z, acc[i][2]);
            acc[i][3] = fmaf(q4[i].y, kv[1].w, acc[i][3]);
            acc[i][0] = fmaf(q4[i].z, kv[2].x, acc[i][0]);
            acc[i][1] = fmaf(q4[i].z, kv[2].y, acc[i][1]);
            acc[i][2] = fmaf(q4[i].z, kv[2].z, acc[i][2]);
            acc[i][3] = fmaf(q4[i].z, kv[2].w, acc[i][3]);
            acc[i][0] = fmaf(q4[i].w, kv[3].x, acc[i][0]);
            acc[i][1] = fmaf(q4[i].w, kv[3].y, acc[i][1]);
            acc[i][2] = fmaf(q4[i].w, kv[3].z, acc[i][2]);
            acc[i][3] = fmaf(q4[i].w, kv[3].w, acc[i][3]);
        }
    }
    const int b_ = bh >> 3, h = bh & 7;
#pragma unroll
    for (int i = 0; i < 4; i++) {
        float z = 1.f / fmaxf(dot[i], 1e-4f);
        int n = nt * 64 + tn + i;
        size_t off = ((size_t)(b_ * NN + n)) * INNER + h * HD + te;
        uint2 H;
        H.x = (uint32_t)__half_as_ushort(__float2half_rn(acc[i][0] * z)) |
              ((uint32_t)__half_as_ushort(__float2half_rn(acc[i][1] * z)) << 16);
        H.y = (uint32_t)__half_as_ushort(__float2half_rn(acc[i][2] * z)) |
              ((uint32_t)__half_as_ushort(__float2half_rn(acc[i][3] * z)) << 16);
        *(uint2*)(g_AT16 + off) = H;
    }
}

// ---------------- launch ----------------
extern "C" void kernel_launch(void* const* d_in, const int* in_sizes, int n_in,
                              void* d_out, int out_size) {
    const float* x = (const float*)d_in[0];
    const float* W_qkv = (const float*)d_in[1];
    const float* W_out = (const float*)d_in[2];
    const float* b_out = (const float*)d_in[3];
    float* out = (float*)d_out;

    static int attr_done = 0;
    if (!attr_done) {
        cudaFuncSetAttribute((const void*)k_gemm_mma<1>,
                             cudaFuncAttributeMaxDynamicSharedMemorySize, SMEM_T);
        cudaFuncSetAttribute((const void*)k_gemm_mma<2>,
                             cudaFuncAttributeMaxDynamicSharedMemorySize, SMEM_T);
        attr_done = 1;
    }

    k_convert<<<(MTOT * DIMK / 4) / 256, 256>>>((const float4*)x, 0, MTOT * DIMK / 4);
    k_convert<<<(1536 * DIMK / 4) / 256, 256>>>((const float4*)W_qkv, 1, 1536 * DIMK / 4);
    k_convert<<<(INNER * INNER / 4) / 256, 256>>>((const float4*)W_out, 2, INNER * INNER / 4);

    dim3 g1(1536 / 128, MTOT / 128);   // x = n-blocks, y = m-blocks
    k_gemm_mma<1><<<g1, 256, SMEM_T>>>(nullptr, nullptr);

    dim3 g2(BHH, 8);
    k_kv<<<g2, 256>>>();
    k_reduce<<<(BHH * HD * HD) / 256, 256>>>();

    dim3 g3(BHH, NN / 64);
    k_attn<<<g3, 256>>>();

    dim3 g4(INNER / 128, MTOT / 128);  // x = n-blocks, y = m-blocks
    k_gemm_mma<2><<<g4, 256, SMEM_T>>>(b_out, out);
}

// round 8
// speedup vs baseline: 4.9091x; 1.3509x over previous
#include <cuda_runtime.h>
#include <cuda_fp16.h>
#include <math.h>
#include <stdint.h>

#define BB    16
#define NN    4096
#define DIMK  512
#define NH    8
#define HD    64
#define INNER 512
#define MTOT  (BB * NN)   // 65536
#define BHH   (BB * NH)   // 128

// ---------------- scratch (static device globals) ----------------
__device__ __align__(256) float g_Q[(size_t)BHH * NN * HD];
__device__ __align__(256) float g_K[(size_t)BHH * NN * HD];
__device__ __align__(256) float g_V[(size_t)BHH * NN * HD];
__device__ __align__(256) __half g_X16[(size_t)MTOT * DIMK];
__device__ __align__(256) __half g_AT16[(size_t)MTOT * INNER];
__device__ __align__(256) __half g_W1[1536 * DIMK];
__device__ __align__(256) __half g_W2[INNER * INNER];
__device__ float g_kvp[8][BHH * HD * HD];
__device__ float g_ksp[8][BHH * HD];
__device__ float g_kv[BHH * HD * HD];
__device__ float g_ksum[BHH * HD];

// ---------------- helpers ----------------
__device__ __forceinline__ uint32_t smem_u32(const void* p) {
    uint32_t a;
    asm("{ .reg .u64 t; cvta.to.shared.u64 t, %1; cvt.u32.u64 %0, t; }" : "=r"(a) : "l"(p));
    return a;
}
__device__ __forceinline__ void cp16(uint32_t dst, const void* src) {
    asm volatile("cp.async.cg.shared.global [%0], [%1], 16;" ::
                 "r"(dst), "l"(__cvta_generic_to_global(src)) : "memory");
}
#define CP_COMMIT() asm volatile("cp.async.commit_group;" ::: "memory")
#define CP_WAIT(n)  asm volatile("cp.async.wait_group %0;" :: "n"(n) : "memory")

#define LDSM4(R, A)                                                          \
    asm volatile("ldmatrix.sync.aligned.m8n8.x4.shared.b16 {%0,%1,%2,%3}, [%4];" \
                 : "=r"((R)[0]), "=r"((R)[1]), "=r"((R)[2]), "=r"((R)[3])    \
                 : "r"(A))

__device__ __forceinline__ void mma16816(float* c, const uint32_t* a, const uint32_t* b) {
    asm volatile(
        "mma.sync.aligned.m16n8k16.row.col.f32.f16.f16.f32 "
        "{%0,%1,%2,%3}, {%4,%5,%6,%7}, {%8,%9}, {%0,%1,%2,%3};"
        : "+f"(c[0]), "+f"(c[1]), "+f"(c[2]), "+f"(c[3])
        : "r"(a[0]), "r"(a[1]), "r"(a[2]), "r"(a[3]), "r"(b[0]), "r"(b[1]));
}

// ---------------- convert fp32 -> fp16 ----------------
__global__ void k_convert(const float4* __restrict__ src, int which, int n4) {
    int i = blockIdx.x * 256 + threadIdx.x;
    if (i >= n4) return;
    float4 v = src[i];
    uint2 H;
    H.x = (uint32_t)__half_as_ushort(__float2half_rn(v.x)) |
          ((uint32_t)__half_as_ushort(__float2half_rn(v.y)) << 16);
    H.y = (uint32_t)__half_as_ushort(__float2half_rn(v.z)) |
          ((uint32_t)__half_as_ushort(__float2half_rn(v.w)) << 16);
    uint2* dst = (which == 0) ? (uint2*)g_X16 : (which == 1) ? (uint2*)g_W1 : (uint2*)g_W2;
    dst[i] = H;
}

// ---------------- single-pass fp16 GEMM, warp tile 32x64, k64 stages ----
// CTA 128x128xK64, 8 warps 4(m) x 2(n), 3 smem buffers, 2 cp.async groups
// in flight, ONE __syncthreads per stage.
#define ROWB 144                  // 64 halves = 128B data + 16B pad
#define ASZ  (128 * ROWB)         // 18432 per tile
#define STAGE_SZ (2 * ASZ)        // A, B = 36864
#define SMEM_T (3 * STAGE_SZ)     // 110592

template <int GEMM_ID>
__global__ __launch_bounds__(256, 2) void k_gemm_mma(const float* __restrict__ bias,
                                                     float* __restrict__ outp) {
    extern __shared__ char smem[];
    const uint32_t sb = smem_u32(smem);
    const int tid = threadIdx.x;
    const int lane = tid & 31;
    const int wid = tid >> 5;
    const int warp_m = wid >> 1;  // 0..3 -> 32 rows each
    const int warp_n = wid & 1;   // 0..1 -> 64 cols each
    const int m0 = blockIdx.y * 128;
    const int n0 = blockIdx.x * 128;

    const __half* A = (GEMM_ID == 1) ? g_X16 : g_AT16;
    const __half* B = (GEMM_ID == 1) ? g_W1 : g_W2;

    float acc[2][8][4];
#pragma unroll
    for (int i = 0; i < 2; i++)
#pragma unroll
        for (int j = 0; j < 8; j++)
#pragma unroll
            for (int k = 0; k < 4; k++) acc[i][j][k] = 0.f;

    // per-thread fixed load coordinates
    const int lr = tid >> 3;          // 0..31 (row group base)
    const int lc = tid & 7;           // 0..7  (16B column)
    const uint32_t so_base = (uint32_t)lr * ROWB + lc * 16;
    const __half* gA = A + (size_t)(m0 + lr) * DIMK + lc * 8;
    const __half* gB = B + (size_t)(n0 + lr) * DIMK + lc * 8;

    auto load_stage = [&](uint32_t st, int k0) {
#pragma unroll
        for (int i = 0; i < 4; i++) {
            uint32_t so = so_base + (uint32_t)i * 32 * ROWB;
            cp16(st + so,       gA + (size_t)(i * 32) * DIMK + k0);
            cp16(st + ASZ + so, gB + (size_t)(i * 32) * DIMK + k0);
        }
        CP_COMMIT();
    };

    load_stage(sb, 0);
    load_stage(sb + STAGE_SZ, 64);

    uint32_t cur = sb;                       // buffer for stage s
    uint32_t nxt2 = sb + 2 * STAGE_SZ;       // buffer for stage s+2

    const int arow = warp_m * 32 + (lane & 15);
    const int grp = lane >> 3;
    const int brow_l = warp_n * 64 + ((grp & 2) << 2) + (lane & 7);
    const uint32_t a_off0 = (uint32_t)arow * ROWB + ((lane >> 4) * 8) * 2;
    const uint32_t b_off0 = (uint32_t)brow_l * ROWB + ((grp & 1) * 8) * 2;

#pragma unroll 1
    for (int s = 0; s < 8; s++) {
        if (s < 7) { CP_WAIT(1); } else { CP_WAIT(0); }
        __syncthreads();
        if (s < 6) {
            load_stage(nxt2, (s + 2) * 64);
            nxt2 += STAGE_SZ;
            if (nxt2 == sb + 3 * STAGE_SZ) nxt2 = sb;
        }
        const uint32_t aT = cur, bT = cur + ASZ;

#pragma unroll
        for (int kk = 0; kk < 4; kk++) {
            uint32_t ah[2][4];
#pragma unroll
            for (int mt = 0; mt < 2; mt++)
                LDSM4(ah[mt], aT + a_off0 + (uint32_t)mt * 16 * ROWB + kk * 32);
            uint32_t bh4[4][4];
#pragma unroll
            for (int np = 0; np < 4; np++)
                LDSM4(bh4[np], bT + b_off0 + (uint32_t)np * 16 * ROWB + kk * 32);
#pragma unroll
            for (int np = 0; np < 4; np++) {
#pragma unroll
                for (int half = 0; half < 2; half++) {
                    const int nt = np * 2 + half;
                    uint32_t bhf[2] = {bh4[np][half * 2], bh4[np][half * 2 + 1]};
#pragma unroll
                    for (int mt = 0; mt < 2; mt++)
                        mma16816(acc[mt][nt], ah[mt], bhf);
                }
            }
        }
        cur += STAGE_SZ;
        if (cur == sb + 3 * STAGE_SZ) cur = sb;
    }

    // ---------------- epilogue ----------------
    const int r0 = lane >> 2;
    const int c0 = (lane & 3) * 2;
#pragma unroll
    for (int mt = 0; mt < 2; mt++) {
#pragma unroll
        for (int nt = 0; nt < 8; nt++) {
            const int col = n0 + warp_n * 64 + nt * 8 + c0;
#pragma unroll
            for (int ri = 0; ri < 2; ri++) {
                const int m = m0 + warp_m * 32 + mt * 16 + r0 + ri * 8;
                float v0 = acc[mt][nt][ri * 2];
                float v1 = acc[mt][nt][ri * 2 + 1];
                if (GEMM_ID == 1) {
                    const int which = col >> 9;
                    const int h = (col >> 6) & 7;
                    const int dd = col & 63;
                    float* dst = (which == 0) ? g_Q : (which == 1) ? g_K : g_V;
                    if (which < 2) {
                        v0 = (v0 > 0.f) ? v0 + 1.f : expf(v0);
                        v1 = (v1 > 0.f) ? v1 + 1.f : expf(v1);
                    }
                    const int b_ = m >> 12, n_ = m & 4095;
                    *(float2*)(dst + ((size_t)(b_ * NH + h) * NN + n_) * HD + dd) =
                        make_float2(v0, v1);
                } else {
                    *(float2*)(outp + (size_t)m * INNER + col) =
                        make_float2(v0 + __ldg(bias + col), v1 + __ldg(bias + col + 1));
                }
            }
        }
    }
}

// ---------------- kv partials ----------------
__global__ __launch_bounds__(256) void k_kv() {
    const int bh = blockIdx.x;
    const int chunk = blockIdx.y;
    const size_t base = ((size_t)bh * NN + (size_t)chunk * (NN / 8)) * HD;
    const float* Kp = g_K + base;
    const float* Vp = g_V + base;
    __shared__ float Ks[32][64];
    __shared__ float Vs[32][64];
    const int tid = threadIdx.x;
    const int td = (tid >> 4) * 4;
    const int te = (tid & 15) * 4;

    float acc[4][4];
#pragma unroll
    for (int i = 0; i < 4; i++)
#pragma unroll
        for (int j = 0; j < 4; j++) acc[i][j] = 0.f;
    float ks[4] = {0.f, 0.f, 0.f, 0.f};
    const bool do_ks = (te == 0);

    for (int nt = 0; nt < NN / 8; nt += 32) {
#pragma unroll
        for (int i = 0; i < 2; i++) {
            int idx = tid + i * 256;
            int r = idx >> 4, c = (idx & 15) * 4;
            *(float4*)&Ks[r][c] = *(const float4*)(Kp + (size_t)(nt + r) * HD + c);
            *(float4*)&Vs[r][c] = *(const float4*)(Vp + (size_t)(nt + r) * HD + c);
        }
        __syncthreads();
#pragma unroll 8
        for (int n = 0; n < 32; n++) {
            float4 kk = *(const float4*)&Ks[n][td];
            float4 vv = *(const float4*)&Vs[n][te];
            float ka[4] = {kk.x, kk.y, kk.z, kk.w};
            float va[4] = {vv.x, vv.y, vv.z, vv.w};
#pragma unroll
            for (int i = 0; i < 4; i++)
#pragma unroll
                for (int j = 0; j < 4; j++)
                    acc[i][j] = fmaf(ka[i], va[j], acc[i][j]);
            if (do_ks) {
                ks[0] += ka[0]; ks[1] += ka[1]; ks[2] += ka[2]; ks[3] += ka[3];
            }
        }
        __syncthreads();
    }

    float* kvp = g_kvp[chunk] + (size_t)bh * HD * HD;
#pragma unroll
    for (int i = 0; i < 4; i++)
        *(float4*)(kvp + (td + i) * HD + te) =
            make_float4(acc[i][0], acc[i][1], acc[i][2], acc[i][3]);
    if (do_ks)
        *(float4*)(g_ksp[chunk] + bh * HD + td) = make_float4(ks[0], ks[1], ks[2], ks[3]);
}

__global__ void k_reduce() {
    int i = blockIdx.x * 256 + threadIdx.x;
    float s = 0.f;
#pragma unroll
    for (int p = 0; p < 8; p++) s += g_kvp[p][i];
    g_kv[i] = s;
    if (i < BHH * HD) {
        float t = 0.f;
#pragma unroll
        for (int p = 0; p < 8; p++) t += g_ksp[p][i];
        g_ksum[i] = t;
    }
}

// ---------------- attn: float4-blocked, fp16 output ----------------
__global__ __launch_bounds__(256) void k_attn() {
    const int bh = blockIdx.x;
    const int nt = blockIdx.y;
    __shared__ float KVs[64][68];
    __shared__ float Qs[64][68];
    __shared__ float KS[64];
    const int tid = threadIdx.x;
    const float* kvp = g_kv + (size_t)bh * HD * HD;
    const float* Qp = g_Q + ((size_t)bh * NN + nt * 64) * HD;
#pragma unroll
    for (int i = 0; i < 4; i++) {
        int idx = tid + i * 256;
        int r = idx >> 4, c = (idx & 15) * 4;
        *(float4*)&KVs[r][c] = *(const float4*)(kvp + r * HD + c);
        *(float4*)&Qs[r][c] = *(const float4*)(Qp + (size_t)r * HD + c);
    }
    if (tid < 64) KS[tid] = g_ksum[bh * HD + tid];
    __syncthreads();

    const int te = (tid & 15) * 4;
    const int tn = (tid >> 4) * 4;
    float acc[4][4];
#pragma unroll
    for (int i = 0; i < 4; i++)
#pragma unroll
        for (int j = 0; j < 4; j++) acc[i][j] = 0.f;
    float dot[4] = {0.f, 0.f, 0.f, 0.f};

#pragma unroll 4
    for (int d4 = 0; d4 < 64; d4 += 4) {
        float4 ks4 = *(const float4*)&KS[d4];
        float4 q4[4], kv[4];
#pragma unroll
        for (int i = 0; i < 4; i++) q4[i] = *(const float4*)&Qs[tn + i][d4];
#pragma unroll
        for (int j = 0; j < 4; j++) kv[j] = *(const float4*)&KVs[d4 + j][te];
#pragma unroll
        for (int i = 0; i < 4; i++) {
            dot[i] = fmaf(q4[i].x, ks4.x, dot[i]);
            dot[i] = fmaf(q4[i].y, ks4.y, dot[i]);
            dot[i] = fmaf(q4[i].z, ks4.z, dot[i]);
            dot[i] = fmaf(q4[i].w, ks4.w, dot[i]);
            acc[i][0] = fmaf(q4[i].x, kv[0].x, acc[i][0]);
            acc[i][1] = fmaf(q4[i].x, kv[0].y, acc[i][1]);
            acc[i][2] = fmaf(q4[i].x, kv[0].z, acc[i][2]);
            acc[i][3] = fmaf(q4[i].x, kv[0].w, acc[i][3]);
            acc[i][0] = fmaf(q4[i].y, kv[1].x, acc[i][0]);
            acc[i][1] = fmaf(q4[i].y, kv[1].y, acc[i][1]);
            acc[i][2] = fmaf(q4[i].y, kv[1].z, acc[i][2]);
            acc[i][3] = fmaf(q4[i].y, kv[1].w, acc[i][3]);
            acc[i][0] = fmaf(q4[i].z, kv[2].x, acc[i][0]);
            acc[i][1] = fmaf(q4[i].z, kv[2].y, acc[i][1]);
            acc[i][2] = fmaf(q4[i].z, kv[2].z, acc[i][2]);
            acc[i][3] = fmaf(q4[i].z, kv[2].w, acc[i][3]);
            acc[i][0] = fmaf(q4[i].w, kv[3].x, acc[i][0]);
            acc[i][1] = fmaf(q4[i].w, kv[3].y, acc[i][1]);
            acc[i][2] = fmaf(q4[i].w, kv[3].z, acc[i][2]);
            acc[i][3] = fmaf(q4[i].w, kv[3].w, acc[i][3]);
        }
    }
    const int b_ = bh >> 3, h = bh & 7;
#pragma unroll
    for (int i = 0; i < 4; i++) {
        float z = 1.f / fmaxf(dot[i], 1e-4f);
        int n = nt * 64 + tn + i;
        size_t off = ((size_t)(b_ * NN + n)) * INNER + h * HD + te;
        uint2 H;
        H.x = (uint32_t)__half_as_ushort(__float2half_rn(acc[i][0] * z)) |
              ((uint32_t)__half_as_ushort(__float2half_rn(acc[i][1] * z)) << 16);
        H.y = (uint32_t)__half_as_ushort(__float2half_rn(acc[i][2] * z)) |
              ((uint32_t)__half_as_ushort(__float2half_rn(acc[i][3] * z)) << 16);
        *(uint2*)(g_AT16 + off) = H;
    }
}

// ---------------- launch ----------------
extern "C" void kernel_launch(void* const* d_in, const int* in_sizes, int n_in,
                              void* d_out, int out_size) {
    const float* x = (const float*)d_in[0];
    const float* W_qkv = (const float*)d_in[1];
    const float* W_out = (const float*)d_in[2];
    const float* b_out = (const float*)d_in[3];
    float* out = (float*)d_out;

    static int attr_done = 0;
    if (!attr_done) {
        cudaFuncSetAttribute((const void*)k_gemm_mma<1>,
                             cudaFuncAttributeMaxDynamicSharedMemorySize, SMEM_T);
        cudaFuncSetAttribute((const void*)k_gemm_mma<2>,
                             cudaFuncAttributeMaxDynamicSharedMemorySize, SMEM_T);
        attr_done = 1;
    }

    k_convert<<<(MTOT * DIMK / 4) / 256, 256>>>((const float4*)x, 0, MTOT * DIMK / 4);
    k_convert<<<(1536 * DIMK / 4) / 256, 256>>>((const float4*)W_qkv, 1, 1536 * DIMK / 4);
    k_convert<<<(INNER * INNER / 4) / 256, 256>>>((const float4*)W_out, 2, INNER * INNER / 4);

    dim3 g1(1536 / 128, MTOT / 128);   // x = n-blocks, y = m-blocks
    k_gemm_mma<1><<<g1, 256, SMEM_T>>>(nullptr, nullptr);

    dim3 g2(BHH, 8);
    k_kv<<<g2, 256>>>();
    k_reduce<<<(BHH * HD * HD) / 256, 256>>>();

    dim3 g3(BHH, NN / 64);
    k_attn<<<g3, 256>>>();

    dim3 g4(INNER / 128, MTOT / 128);  // x = n-blocks, y = m-blocks
    k_gemm_mma<2><<<g4, 256, SMEM_T>>>(b_out, out);
}

// round 9
// speedup vs baseline: 6.2335x; 1.2698x over previous
#include <cuda_runtime.h>
#include <cuda_fp16.h>
#include <math.h>
#include <stdint.h>

#define BB    16
#define NN    4096
#define DIMK  512
#define NH    8
#define HD    64
#define INNER 512
#define MTOT  (BB * NN)   // 65536
#define BHH   (BB * NH)   // 128
#define EVW   80          // kv columns: 64 V + 1 ones(ksum) + 15 pad

// ---------------- scratch ----------------
__device__ __align__(256) __half g_Q16[(size_t)BHH * NN * HD];
__device__ __align__(256) __half g_K16[(size_t)BHH * NN * HD];
__device__ __align__(256) __half g_V16[(size_t)BHH * NN * HD];
__device__ __align__(256) __half g_X16[(size_t)MTOT * DIMK];
__device__ __align__(256) __half g_AT16[(size_t)MTOT * INNER];
__device__ __align__(256) __half g_W1[1536 * DIMK];
__device__ __align__(256) __half g_W2[INNER * INNER];
__device__ float g_kvp[8][BHH * HD * EVW];
__device__ __align__(256) __half g_kvTh[BHH * EVW * HD];   // [bh][e][d]
__device__ __align__(256) __half g_kvTl[BHH * EVW * HD];

// ---------------- helpers ----------------
__device__ __forceinline__ uint32_t smem_u32(const void* p) {
    uint32_t a;
    asm("{ .reg .u64 t; cvta.to.shared.u64 t, %1; cvt.u32.u64 %0, t; }" : "=r"(a) : "l"(p));
    return a;
}
__device__ __forceinline__ void cp16(uint32_t dst, const void* src) {
    asm volatile("cp.async.cg.shared.global [%0], [%1], 16;" ::
                 "r"(dst), "l"(__cvta_generic_to_global(src)) : "memory");
}
#define CP_COMMIT() asm volatile("cp.async.commit_group;" ::: "memory")
#define CP_WAIT(n)  asm volatile("cp.async.wait_group %0;" :: "n"(n) : "memory")

#define LDSM4(R, A)                                                              \
    asm volatile("ldmatrix.sync.aligned.m8n8.x4.shared.b16 {%0,%1,%2,%3}, [%4];" \
                 : "=r"((R)[0]), "=r"((R)[1]), "=r"((R)[2]), "=r"((R)[3])        \
                 : "r"(A))
#define LDSM4T(R, A)                                                                   \
    asm volatile("ldmatrix.sync.aligned.m8n8.x4.trans.shared.b16 {%0,%1,%2,%3}, [%4];" \
                 : "=r"((R)[0]), "=r"((R)[1]), "=r"((R)[2]), "=r"((R)[3])              \
                 : "r"(A))

__device__ __forceinline__ void mma16816(float* c, const uint32_t* a, const uint32_t* b) {
    asm volatile(
        "mma.sync.aligned.m16n8k16.row.col.f32.f16.f16.f32 "
        "{%0,%1,%2,%3}, {%4,%5,%6,%7}, {%8,%9}, {%0,%1,%2,%3};"
        : "+f"(c[0]), "+f"(c[1]), "+f"(c[2]), "+f"(c[3])
        : "r"(a[0]), "r"(a[1]), "r"(a[2]), "r"(a[3]), "r"(b[0]), "r"(b[1]));
}

// ---------------- convert fp32 -> fp16 ----------------
__global__ void k_convert(const float4* __restrict__ src, int which, int n4) {
    int i = blockIdx.x * 256 + threadIdx.x;
    if (i >= n4) return;
    float4 v = src[i];
    uint2 H;
    H.x = (uint32_t)__half_as_ushort(__float2half_rn(v.x)) |
          ((uint32_t)__half_as_ushort(__float2half_rn(v.y)) << 16);
    H.y = (uint32_t)__half_as_ushort(__float2half_rn(v.z)) |
          ((uint32_t)__half_as_ushort(__float2half_rn(v.w)) << 16);
    uint2* dst = (which == 0) ? (uint2*)g_X16 : (which == 1) ? (uint2*)g_W1 : (uint2*)g_W2;
    dst[i] = H;
}

// ---------------- single-pass fp16 GEMM (same mainloop as R8) ----------------
#define ROWB 144
#define ASZ  (128 * ROWB)
#define STAGE_SZ (2 * ASZ)
#define SMEM_T (3 * STAGE_SZ)

template <int GEMM_ID>
__global__ __launch_bounds__(256, 2) void k_gemm_mma(const float* __restrict__ bias,
                                                     float* __restrict__ outp) {
    extern __shared__ char smem[];
    const uint32_t sb = smem_u32(smem);
    const int tid = threadIdx.x;
    const int lane = tid & 31;
    const int wid = tid >> 5;
    const int warp_m = wid >> 1;
    const int warp_n = wid & 1;
    const int m0 = blockIdx.y * 128;
    const int n0 = blockIdx.x * 128;

    const __half* A = (GEMM_ID == 1) ? g_X16 : g_AT16;
    const __half* B = (GEMM_ID == 1) ? g_W1 : g_W2;
    const int KD = (GEMM_ID == 1) ? DIMK : INNER;

    float acc[2][8][4];
#pragma unroll
    for (int i = 0; i < 2; i++)
#pragma unroll
        for (int j = 0; j < 8; j++)
#pragma unroll
            for (int k = 0; k < 4; k++) acc[i][j][k] = 0.f;

    const int lr = tid >> 3;
    const int lc = tid & 7;
    const uint32_t so_base = (uint32_t)lr * ROWB + lc * 16;
    const __half* gA = A + (size_t)(m0 + lr) * KD + lc * 8;
    const __half* gB = B + (size_t)(n0 + lr) * KD + lc * 8;

    auto load_stage = [&](uint32_t st, int k0) {
#pragma unroll
        for (int i = 0; i < 4; i++) {
            uint32_t so = so_base + (uint32_t)i * 32 * ROWB;
            cp16(st + so,       gA + (size_t)(i * 32) * KD + k0);
            cp16(st + ASZ + so, gB + (size_t)(i * 32) * KD + k0);
        }
        CP_COMMIT();
    };

    load_stage(sb, 0);
    load_stage(sb + STAGE_SZ, 64);

    uint32_t cur = sb;
    uint32_t nxt2 = sb + 2 * STAGE_SZ;

    const int arow = warp_m * 32 + (lane & 15);
    const int grp = lane >> 3;
    const int brow_l = warp_n * 64 + ((grp & 2) << 2) + (lane & 7);
    const uint32_t a_off0 = (uint32_t)arow * ROWB + ((lane >> 4) * 8) * 2;
    const uint32_t b_off0 = (uint32_t)brow_l * ROWB + ((grp & 1) * 8) * 2;

#pragma unroll 1
    for (int s = 0; s < 8; s++) {
        if (s < 7) { CP_WAIT(1); } else { CP_WAIT(0); }
        __syncthreads();
        if (s < 6) {
            load_stage(nxt2, (s + 2) * 64);
            nxt2 += STAGE_SZ;
            if (nxt2 == sb + 3 * STAGE_SZ) nxt2 = sb;
        }
        const uint32_t aT = cur, bT = cur + ASZ;

#pragma unroll
        for (int kk = 0; kk < 4; kk++) {
            uint32_t ah[2][4];
#pragma unroll
            for (int mt = 0; mt < 2; mt++)
                LDSM4(ah[mt], aT + a_off0 + (uint32_t)mt * 16 * ROWB + kk * 32);
            uint32_t bh4[4][4];
#pragma unroll
            for (int np = 0; np < 4; np++)
                LDSM4(bh4[np], bT + b_off0 + (uint32_t)np * 16 * ROWB + kk * 32);
#pragma unroll
            for (int np = 0; np < 4; np++) {
#pragma unroll
                for (int half = 0; half < 2; half++) {
                    const int nt = np * 2 + half;
                    uint32_t bhf[2] = {bh4[np][half * 2], bh4[np][half * 2 + 1]};
#pragma unroll
                    for (int mt = 0; mt < 2; mt++)
                        mma16816(acc[mt][nt], ah[mt], bhf);
                }
            }
        }
        cur += STAGE_SZ;
        if (cur == sb + 3 * STAGE_SZ) cur = sb;
    }

    // ---------------- epilogue ----------------
    const int r0 = lane >> 2;
    const int c0 = (lane & 3) * 2;
#pragma unroll
    for (int mt = 0; mt < 2; mt++) {
#pragma unroll
        for (int nt = 0; nt < 8; nt++) {
            const int col = n0 + warp_n * 64 + nt * 8 + c0;
#pragma unroll
            for (int ri = 0; ri < 2; ri++) {
                const int m = m0 + warp_m * 32 + mt * 16 + r0 + ri * 8;
                float v0 = acc[mt][nt][ri * 2];
                float v1 = acc[mt][nt][ri * 2 + 1];
                if (GEMM_ID == 1) {
                    const int which = col >> 9;
                    const int h = (col >> 6) & 7;
                    const int dd = col & 63;
                    __half* dst = (which == 0) ? g_Q16 : (which == 1) ? g_K16 : g_V16;
                    if (which < 2) {
                        v0 = (v0 > 0.f) ? v0 + 1.f : expf(v0);
                        v1 = (v1 > 0.f) ? v1 + 1.f : expf(v1);
                    }
                    const int b_ = m >> 12, n_ = m & 4095;
                    *(__half2*)(dst + ((size_t)(b_ * NH + h) * NN + n_) * HD + dd) =
                        __floats2half2_rn(v0, v1);
                } else {
                    *(float2*)(outp + (size_t)m * INNER + col) =
                        make_float2(v0 + __ldg(bias + col), v1 + __ldg(bias + col + 1));
                }
            }
        }
    }
}

// ---------------- k_kv: MMA, C[64d x 80e'] = K^T [V|1|0], partials per chunk ----
#define KSTR 144
#define VSTR 176
#define KTILE (64 * KSTR)
#define VTILE (64 * VSTR)

__global__ __launch_bounds__(128) void k_kv() {
    __shared__ char sm[2 * KTILE + 2 * VTILE];
    const uint32_t sK = smem_u32(sm);
    const uint32_t sV = sK + 2 * KTILE;
    const int bh = blockIdx.x;
    const int chunk = blockIdx.y;
    const int tid = threadIdx.x;
    const int lane = tid & 31;
    const int warp = tid >> 5;

    const __half* Kg = g_K16 + ((size_t)bh * NN + chunk * 512) * HD;
    const __half* Vg = g_V16 + ((size_t)bh * NN + chunk * 512) * HD;

    // init ones/pad columns of both V buffers (cols 64..79)
    {
        int r = tid & 63, buf = tid >> 6;
        uint32_t base = sV + buf * VTILE + r * VSTR + 128;
        *(uint4*)(sm + (base - sK)) = make_uint4(0x00003c00u, 0u, 0u, 0u);  // {1.0h,0,...}
        *(uint4*)(sm + (base - sK) + 16) = make_uint4(0u, 0u, 0u, 0u);
    }

    auto load = [&](int buf, int t) {
        const __half* kp = Kg + (size_t)t * 64 * HD;
        const __half* vp = Vg + (size_t)t * 64 * HD;
#pragma unroll
        for (int i = 0; i < 4; i++) {
            int idx = tid + i * 128;
            int r = idx >> 3, c = idx & 7;
            cp16(sK + buf * KTILE + r * KSTR + c * 16, kp + r * HD + c * 8);
            cp16(sV + buf * VTILE + r * VSTR + c * 16, vp + r * HD + c * 8);
        }
        CP_COMMIT();
    };

    float acc[10][4];
#pragma unroll
    for (int i = 0; i < 10; i++)
#pragma unroll
        for (int j = 0; j < 4; j++) acc[i][j] = 0.f;

    const int i7 = lane & 7;
    const int s4 = lane >> 3;
    // A = K^T: group s: row n0 + i7 + ((s>>1)<<3), col 16*warp + ((s&1)<<3)
    const uint32_t aoff = (uint32_t)(i7 + ((s4 >> 1) << 3)) * KSTR +
                          (16 * warp + ((s4 & 1) << 3)) * 2;
    // B = [V|1]: group s: row n0 + i7 + ((s&1)<<3), col 16*eb + ((s>>1)<<3)
    const uint32_t boff = (uint32_t)(i7 + ((s4 & 1) << 3)) * VSTR + ((s4 >> 1) << 3) * 2;

    load(0, 0);
#pragma unroll 1
    for (int t = 0; t < 8; t++) {
        if (t < 7) load((t + 1) & 1, t + 1);
        if (t < 7) { CP_WAIT(1); } else { CP_WAIT(0); }
        __syncthreads();
        const uint32_t kb = sK + (t & 1) * KTILE;
        const uint32_t vb = sV + (t & 1) * VTILE;
#pragma unroll
        for (int n0 = 0; n0 < 64; n0 += 16) {
            uint32_t a[4];
            LDSM4T(a, kb + aoff + n0 * KSTR);
#pragma unroll
            for (int eb = 0; eb < 5; eb++) {
                uint32_t b[4];
                LDSM4T(b, vb + boff + n0 * VSTR + eb * 32);
                mma16816(acc[2 * eb], a, b);
                mma16816(acc[2 * eb + 1], a, b + 2);
            }
        }
        __syncthreads();
    }

    float* o = g_kvp[chunk] + (size_t)bh * HD * EVW;
    const int d0 = 16 * warp + (lane >> 2);
    const int e0 = 2 * (lane & 3);
#pragma unroll
    for (int nt = 0; nt < 10; nt++) {
        int e = nt * 8 + e0;
        *(float2*)(o + d0 * EVW + e) = make_float2(acc[nt][0], acc[nt][1]);
        *(float2*)(o + (d0 + 8) * EVW + e) = make_float2(acc[nt][2], acc[nt][3]);
    }
}

// ---------------- reduce partials -> kvT hi/lo fp16 [bh][e][d] ----------------
__global__ void k_reduce() {
    int idx = blockIdx.x * 256 + threadIdx.x;   // 128*80*64
    int bh = idx / (EVW * HD);
    int r = idx % (EVW * HD);
    int e = r >> 6, d = r & 63;
    size_t in = (size_t)bh * HD * EVW + d * EVW + e;
    float s = 0.f;
#pragma unroll
    for (int p = 0; p < 8; p++) s += g_kvp[p][in];
    __half hi = __float2half_rn(s);
    g_kvTh[idx] = hi;
    g_kvTl[idx] = __float2half_rn(s - __half2float(hi));
}

// ---------------- k_attn: MMA, out = Q @ kvT^T (hi+lo), z from col 64 ----------
__global__ __launch_bounds__(128) void k_attn() {
    __shared__ char sm[64 * KSTR + 2 * EVW * KSTR];
    const uint32_t sQ = smem_u32(sm);
    const uint32_t sH = sQ + 64 * KSTR;
    const uint32_t sL = sH + EVW * KSTR;
    const int bh = blockIdx.x;
    const int tile = blockIdx.y;
    const int tid = threadIdx.x;
    const int lane = tid & 31;
    const int warp = tid >> 5;

    const __half* Qg = g_Q16 + ((size_t)bh * NN + tile * 64) * HD;
    const __half* Hg = g_kvTh + (size_t)bh * EVW * HD;
    const __half* Lg = g_kvTl + (size_t)bh * EVW * HD;

#pragma unroll
    for (int i = 0; i < 4; i++) {
        int idx = tid + i * 128;
        int r = idx >> 3, c = idx & 7;
        cp16(sQ + r * KSTR + c * 16, Qg + r * HD + c * 8);
    }
#pragma unroll
    for (int i = 0; i < 5; i++) {
        int idx = tid + i * 128;
        int r = idx >> 3, c = idx & 7;
        cp16(sH + r * KSTR + c * 16, Hg + r * HD + c * 8);
        cp16(sL + r * KSTR + c * 16, Lg + r * HD + c * 8);
    }
    CP_COMMIT();
    CP_WAIT(0);
    __syncthreads();

    float acc[10][4];
#pragma unroll
    for (int i = 0; i < 10; i++)
#pragma unroll
        for (int j = 0; j < 4; j++) acc[i][j] = 0.f;

    const int grp = lane >> 3;
    const uint32_t a_off0 = (uint32_t)(warp * 16 + (lane & 15)) * KSTR + ((lane >> 4) * 8) * 2;
    const uint32_t b_off0 = (uint32_t)(((grp & 2) << 2) + (lane & 7)) * KSTR + ((grp & 1) * 8) * 2;

#pragma unroll
    for (int kk = 0; kk < 4; kk++) {
        uint32_t a[4];
        LDSM4(a, sQ + a_off0 + kk * 32);
#pragma unroll
        for (int pass = 0; pass < 2; pass++) {
            const uint32_t base = (pass == 0) ? sH : sL;
#pragma unroll
            for (int eb = 0; eb < 5; eb++) {
                uint32_t b[4];
                LDSM4(b, base + b_off0 + (uint32_t)(16 * eb) * KSTR + kk * 32);
                mma16816(acc[2 * eb], a, b);
                mma16816(acc[2 * eb + 1], a, b + 2);
            }
        }
    }

    // z from column 64 (acc[8], c0==64 held by lanes with lane&3==0)
    float d0v = __shfl_sync(0xffffffffu, acc[8][0], lane & ~3);
    float d1v = __shfl_sync(0xffffffffu, acc[8][2], lane & ~3);
    float z0 = 1.f / fmaxf(d0v, 1e-4f);
    float z1 = 1.f / fmaxf(d1v, 1e-4f);

    const int b_ = bh >> 3, h = bh & 7;
    const int n0g = tile * 64 + warp * 16 + (lane >> 2);
    __half* o = g_AT16 + ((size_t)(b_ * NN) + n0g) * INNER + h * HD;
#pragma unroll
    for (int nt = 0; nt < 8; nt++) {
        int col = nt * 8 + 2 * (lane & 3);
        *(__half2*)(o + col) = __floats2half2_rn(acc[nt][0] * z0, acc[nt][1] * z0);
        *(__half2*)(o + 8 * INNER + col) = __floats2half2_rn(acc[nt][2] * z1, acc[nt][3] * z1);
    }
}

// ---------------- launch ----------------
extern "C" void kernel_launch(void* const* d_in, const int* in_sizes, int n_in,
                              void* d_out, int out_size) {
    const float* x = (const float*)d_in[0];
    const float* W_qkv = (const float*)d_in[1];
    const float* W_out = (const float*)d_in[2];
    const float* b_out = (const float*)d_in[3];
    float* out = (float*)d_out;

    static int attr_done = 0;
    if (!attr_done) {
        cudaFuncSetAttribute((const void*)k_gemm_mma<1>,
                             cudaFuncAttributeMaxDynamicSharedMemorySize, SMEM_T);
        cudaFuncSetAttribute((const void*)k_gemm_mma<2>,
                             cudaFuncAttributeMaxDynamicSharedMemorySize, SMEM_T);
        attr_done = 1;
    }

    k_convert<<<(MTOT * DIMK / 4) / 256, 256>>>((const float4*)x, 0, MTOT * DIMK / 4);
    k_convert<<<(1536 * DIMK / 4) / 256, 256>>>((const float4*)W_qkv, 1, 1536 * DIMK / 4);
    k_convert<<<(INNER * INNER / 4) / 256, 256>>>((const float4*)W_out, 2, INNER * INNER / 4);

    dim3 g1(1536 / 128, MTOT / 128);
    k_gemm_mma<1><<<g1, 256, SMEM_T>>>(nullptr, nullptr);

    dim3 g2(BHH, 8);
    k_kv<<<g2, 128>>>();

    k_reduce<<<(BHH * EVW * HD) / 256, 256>>>();

    dim3 g3(BHH, NN / 64);
    k_attn<<<g3, 128>>>();

    dim3 g4(INNER / 128, MTOT / 128);
    k_gemm_mma<2><<<g4, 256, SMEM_T>>>(b_out, out);
}